// round 8
// baseline (speedup 1.0000x reference)
#include <cuda_runtime.h>
#include <cuda_fp16.h>
#include <math.h>
#include <stdint.h>

// ---------------------------------------------------------------------------
// TwoDimensionalSSM: out = silu( conv4dir(x, k) + x*omega )
// M_n is 2-level Toeplitz: M[(i,j),(u,v)] = T_n(i-u, j-v), T = 63x63 table.
// GEMM Out_n = M_n @ X_n^T with A fragments generated from the smem table.
// ---------------------------------------------------------------------------

#define LSIDE  32
#define SEQ    1024
#define BSZ    32
#define EMBED  512
#define NSSM   32
#define KDIM   128
#define GROUPS 32
#define GCOLS  512
#define TROWS  63
#define TCOLSW 64          // padded row width
#define TSZ    (TROWS * TCOLSW)   // 4032 uint32 per group

// Static device scratch (allocation-free, graph-capturable)
__device__ float  g_kpart[2][KDIM][SEQ];                             // 1 MB
__device__ __align__(16) uint32_t g_Tp[(size_t)GROUPS * TSZ];        // 516 KB pair tables
__device__ __align__(16) __half g_X[(size_t)GROUPS * GCOLS * 1024];  // 32 MB  [n][c][s]
__device__ __align__(16) __half g_Outh[(size_t)GROUPS * 1024 * GCOLS]; // 32 MB [n][sp][c]

__device__ __forceinline__ float sigmoidf_(float v) { return 1.0f / (1.0f + expf(-v)); }

__device__ __forceinline__ uint32_t smem_u32(const void* p) {
    return (uint32_t)__cvta_generic_to_shared(p);
}
__device__ __forceinline__ void cp_async16(uint32_t dst, const void* src) {
    asm volatile("cp.async.cg.shared.global [%0], [%1], 16;" :: "r"(dst), "l"(src) : "memory");
}
__device__ __forceinline__ void cp_commit() {
    asm volatile("cp.async.commit_group;" ::: "memory");
}
__device__ __forceinline__ uint32_t lds32(uint32_t addr) {
    uint32_t v;
    asm volatile("ld.shared.b32 %0, [%1];" : "=r"(v) : "r"(addr));
    return v;
}
__device__ __forceinline__ void ldsm_x4(uint32_t* r, uint32_t addr) {
    asm volatile("ldmatrix.sync.aligned.m8n8.x4.shared.b16 {%0,%1,%2,%3}, [%4];"
                 : "=r"(r[0]), "=r"(r[1]), "=r"(r[2]), "=r"(r[3]) : "r"(addr));
}
__device__ __forceinline__ void mma16816(float* c, const uint32_t* a, uint32_t b0, uint32_t b1) {
    asm volatile(
        "mma.sync.aligned.m16n8k16.row.col.f32.f16.f16.f32 "
        "{%0,%1,%2,%3}, {%4,%5,%6,%7}, {%8,%9}, {%0,%1,%2,%3};"
        : "+f"(c[0]), "+f"(c[1]), "+f"(c[2]), "+f"(c[3])
        : "r"(a[0]), "r"(a[1]), "r"(a[2]), "r"(a[3]), "r"(b0), "r"(b1));
}

// ---------------------------------------------------------------------------
// Kernel 1: 2-D SSM recurrence -> impulse response partials per (h, state n).
// ---------------------------------------------------------------------------
__global__ void compute_k_kernel(const float* __restrict__ A1p, const float* __restrict__ A2p,
                                 const float* __restrict__ A3p, const float* __restrict__ A4p,
                                 const float* __restrict__ B1p, const float* __restrict__ B2p,
                                 const float* __restrict__ C1p, const float* __restrict__ C2p) {
    int g = blockIdx.x * blockDim.x + threadIdx.x;
    if (g >= 2 * KDIM) return;
    int h = g >> 1, nn = g & 1;
    int idx = h * 2 + nn;
    float A1 = sigmoidf_(A1p[idx]);
    float A2 = sigmoidf_(A2p[idx]);
    float A3 = sigmoidf_(A3p[idx]);
    float A4 = sigmoidf_(A4p[idx]);
    float B1 = sigmoidf_(B1p[idx]);
    float B2 = sigmoidf_(B2p[idx]);
    const float scale = 0.70710678118654752f;
    float C1 = C1p[idx] * scale;
    float C2 = C2p[idx] * scale;

    float xh_up[LSIDE], xv_up[LSIDE];
#pragma unroll
    for (int j = 0; j < LSIDE; j++) { xh_up[j] = 0.0f; xv_up[j] = 0.0f; }

    float* kout = &g_kpart[nn][h][0];
    for (int i = 0; i < LSIDE; i++) {
        float xh_prev = 0.0f, xv_prev = 0.0f;
        for (int j = 0; j < LSIDE; j++) {
            float u = (i == 0 && j == 0) ? 1.0f : 0.0f;
            float xv_new  = A3 * xh_up[j] + A4 * xv_up[j] + B2 * u;
            float xv_left = (j == 0) ? 0.0f : xv_prev;
            float xh_new  = A1 * xh_prev + A2 * xv_left + B1 * u;
            kout[i * LSIDE + j] = C1 * xh_new + C2 * xv_new;
            xh_up[j] = xh_new; xv_up[j] = xv_new;
            xh_prev  = xh_new; xv_prev  = xv_new;
        }
    }
}

// ---------------------------------------------------------------------------
// Kernel 2: build Toeplitz pair tables.
//  Spair[da+31][p] = half2( T[da][32-p], T[da][31-p] )   (p = 32 - db)
// ---------------------------------------------------------------------------
__global__ __launch_bounds__(256) void build_T_kernel() {
    int n = blockIdx.x;
    __shared__ float sk[4][1024];
    int tid = threadIdx.x;
#pragma unroll
    for (int it = 0; it < 16; it++) {
        int idx = tid + it * 256;
        int d  = idx >> 10;
        int ab = idx & 1023;
        int a = ab >> 5, b = ab & 31;
        float v = g_kpart[0][d * NSSM + n][ab] + g_kpart[1][d * NSSM + n][ab];
        float f = 1.0f;
        if (!(a == 0 && b == 0)) {
            if (a == 0) f *= 2.0f;
            if (b == 0) f *= 2.0f;
        }
        sk[d][ab] = v * f;
    }
    __syncthreads();

    auto Tval = [&](int da, int db) -> float {
        if (db > 31 || db < -31) return 0.0f;
        int a = da < 0 ? -da : da;
        int b = db < 0 ? -db : db;
        int idx = a * 32 + b;
        float r = 0.0f;
        if (da >= 0 && db >= 0) r += sk[0][idx];
        if (da <= 0 && db >= 0) r += sk[1][idx];
        if (da >= 0 && db <= 0) r += sk[2][idx];
        if (da <= 0 && db <= 0) r += sk[3][idx];
        return r;
    };

#pragma unroll
    for (int t = 0; t < 16; t++) {
        int e = tid + t * 256;
        if (e < TSZ) {
            int da = (e >> 6) - 31;
            int p  = e & 63;
            __half2 h = __floats2half2_rn(Tval(da, 32 - p), Tval(da, 31 - p));
            g_Tp[(size_t)n * TSZ + e] = *(uint32_t*)&h;
        }
    }
}

// ---------------------------------------------------------------------------
// Kernel 3: gather/transpose x (S,B,E) fp32 -> g_X[n][c][s] fp16  (c=b*16+e/32)
// ---------------------------------------------------------------------------
__global__ __launch_bounds__(256) void transpose_kernel(const float* __restrict__ x) {
    __shared__ __half sm[32][520];
    int b  = blockIdx.x & 31;
    int s0 = (blockIdx.x >> 5) << 5;
    int t = threadIdx.x;
#pragma unroll
    for (int i = 0; i < 64; ++i) {
        int idx = t + (i << 8);
        int si = idx >> 9, e = idx & 511;
        sm[si][e] = __float2half_rn(x[(size_t)(s0 + si) * (BSZ * EMBED) + (size_t)b * EMBED + e]);
    }
    __syncthreads();
#pragma unroll
    for (int i = 0; i < 8; ++i) {
        int c2 = t + (i << 8);
        int pair = c2 >> 2, sj = (c2 & 3) << 3;
        int nn = pair & 31, r = pair >> 5;
        int e = (r << 5) + nn;
        __half tmp[8];
#pragma unroll
        for (int q = 0; q < 8; ++q) tmp[q] = sm[sj + q][e];
        *(uint4*)&g_X[((size_t)nn * GCOLS + b * 16 + r) * 1024 + s0 + sj] = *(uint4*)tmp;
    }
}

// ---------------------------------------------------------------------------
// Kernel 4: Toeplitz HMMA GEMM. CTA tile 256(M)x128(N), 512 threads,
// 16 warps (8M x 2N), warp tile 32x64. BK=64, 16 chunks, double-buffered B
// (2 x 16KB) + Spair table (16128B) = ~48KB. A fragments from the table.
// ---------------------------------------------------------------------------
__global__ __launch_bounds__(512) void gemm_kernel() {
    __shared__ __align__(1024) __half bbuf[2 * 128 * 64];   // 32 KB B stages
    __shared__ __align__(16) uint32_t spair[TSZ];           // 16128 B table

    const int n  = blockIdx.z;
    const int m0 = blockIdx.y << 8;       // 256-row tile
    const int n0 = blockIdx.x << 7;
    const __half* Bg = g_X + ((size_t)n << 19);

    const int tid = threadIdx.x;
    const int wid = tid >> 5;
    const int lane = tid & 31;
    const int wm = wid & 7;          // 8 warps along M (32 rows each)
    const int wn = wid >> 3;         // 2 warps along N (64 cols each)

    const uint32_t sB = smem_u32(bbuf);
    const uint32_t sT = smem_u32(spair);
    const uint32_t B_STG = 16384;

    // table load (cp.async group 0)
    {
        const uint32_t* src = g_Tp + (size_t)n * TSZ;
#pragma unroll
        for (int i = 0; i < 2; ++i) {
            int id = tid + (i << 9);
            if (id < TSZ / 4) cp_async16(sT + id * 16, src + id * 4);
        }
        cp_commit();
    }

    auto load_chunk = [&](int c, int st) {
        int k0 = c << 6;
#pragma unroll
        for (int i = 0; i < 2; ++i) {            // B: 128 rows x 8 x 16B
            int id  = tid + (i << 9);            // 0..1023
            int row = id >> 3, k8 = id & 7;
            uint32_t sw = (uint32_t)(row * 128 + ((k8 << 4) ^ ((row & 7) << 4)));
            cp_async16(sB + (uint32_t)st * B_STG + sw,
                       Bg + (size_t)(n0 + row) * 1024 + k0 + (k8 << 3));
        }
        cp_commit();
    };

    load_chunk(0, 0);
    load_chunk(1, 1);

    float acc[2][8][4];
#pragma unroll
    for (int mi = 0; mi < 2; mi++)
#pragma unroll
        for (int nj = 0; nj < 8; nj++)
#pragma unroll
            for (int q = 0; q < 4; q++) acc[mi][nj][q] = 0.0f;

    // A base addresses: per mi, two rows (r, r+8) of the 16x16 fragment.
    // base = &Spair[(i+31)*64 + (32 - j) + (lane&3)*2]  (bytes)
    uint32_t pA[2][2];
#pragma unroll
    for (int mi = 0; mi < 2; mi++) {
#pragma unroll
        for (int rh = 0; rh < 2; rh++) {
            int sp = m0 + wm * 32 + mi * 16 + (lane >> 2) + rh * 8;
            int i = sp >> 5, j = sp & 31;
            pA[mi][rh] = sT + (uint32_t)(((i + 31) * 64 + (32 - j) + (lane & 3) * 2) * 4);
        }
    }

    // B ldmatrix lane geometry
    const int bRow0 = wn * 64 + (lane & 7) + ((lane & 16) >> 1);   // + p*16
    const uint32_t bKsel = (uint32_t)((lane & 8) << 1);            // 0 or 16 bytes

    for (int c = 0; c < 16; ++c) {
        if (c < 14)       asm volatile("cp.async.wait_group 1;" ::: "memory");
        else              asm volatile("cp.async.wait_group 0;" ::: "memory");
        __syncthreads();

        uint32_t bS = sB + (uint32_t)(c & 1) * B_STG;

#pragma unroll
        for (int ks = 0; ks < 4; ++ks) {
            int u = 2 * c + (ks >> 1);
            int aoff = ((ks & 1) << 6) - (u << 8);   // ((ks&1)*16)*4 - u*64*4 bytes

            uint32_t a[2][4];
#pragma unroll
            for (int mi = 0; mi < 2; mi++) {
                a[mi][0] = lds32(pA[mi][0] + aoff);        // (r,   k lo8)
                a[mi][1] = lds32(pA[mi][1] + aoff);        // (r+8, k lo8)
                a[mi][2] = lds32(pA[mi][0] + aoff + 32);   // (r,   k hi8)
                a[mi][3] = lds32(pA[mi][1] + aoff + 32);   // (r+8, k hi8)
            }
            uint32_t b[4][4];
#pragma unroll
            for (int p = 0; p < 4; p++) {
                int row = bRow0 + p * 16;
                uint32_t kb = (uint32_t)(ks << 5) + bKsel;
                uint32_t addr = bS + (uint32_t)(row * 128)
                              + (kb ^ (uint32_t)((row & 7) << 4));
                ldsm_x4(b[p], addr);
            }
#pragma unroll
            for (int mi = 0; mi < 2; mi++)
#pragma unroll
                for (int nj = 0; nj < 8; nj++) {
                    int p = nj >> 1, e = (nj & 1) << 1;
                    mma16816(acc[mi][nj], a[mi], b[p][e], b[p][e + 1]);
                }
        }
        __syncthreads();
        if (c + 2 < 16) load_chunk(c + 2, c & 1);
    }

    // writeout accumulators as fp16 pairs
    __half* C = g_Outh + ((size_t)n << 19);
    int colBase = n0 + wn * 64 + ((lane & 3) << 1);
    int rowBase = m0 + wm * 32 + (lane >> 2);
#pragma unroll
    for (int mi = 0; mi < 2; mi++) {
        int r = rowBase + mi * 16;
#pragma unroll
        for (int nj = 0; nj < 8; nj++) {
            int col = colBase + nj * 8;
            __half2 lo = __floats2half2_rn(acc[mi][nj][0], acc[mi][nj][1]);
            __half2 hi = __floats2half2_rn(acc[mi][nj][2], acc[mi][nj][3]);
            *(__half2*)&C[(size_t)r * GCOLS + col]       = lo;
            *(__half2*)&C[(size_t)(r + 8) * GCOLS + col] = hi;
        }
    }
}

// ---------------------------------------------------------------------------
// Kernel 5: un-gather Out(fp16) + residual x*omega + SiLU -> d_out fp32
// ---------------------------------------------------------------------------
__global__ __launch_bounds__(512) void epilogue_kernel(const float* __restrict__ x,
                                                       const float* __restrict__ omega,
                                                       float* __restrict__ out) {
    int blk = blockIdx.x;                 // 0..8191
    int b  = blk & 31;
    int s0 = (blk >> 5) << 2;             // 4 consecutive s
    __shared__ float sm[4][16 * 33 + 33];
    int tid = threadIdx.x;                // 512
#pragma unroll
    for (int pass = 0; pass < 2; pass++) {
        int sv = ((tid >> 8) << 1) + pass;   // covers 0..3 over 2 passes
        int q  = tid & 255;
        int nn = q >> 3, rr = (q & 7) << 1;
        __half2 v = *(const __half2*)&g_Outh[((size_t)nn << 19)
                                             + (size_t)(s0 + sv) * GCOLS + b * 16 + rr];
        sm[sv][rr * 33 + nn]       = __low2float(v);
        sm[sv][(rr + 1) * 33 + nn] = __high2float(v);
    }
    __syncthreads();
    float om = omega[tid];
    int sidx = (tid >> 5) * 33 + (tid & 31);
#pragma unroll
    for (int sv = 0; sv < 4; sv++) {
        size_t off = (size_t)(s0 + sv) * (BSZ * EMBED) + (size_t)b * EMBED + tid;
        float z = sm[sv][sidx] + x[off] * om;
        out[off] = z / (1.0f + expf(-z));
    }
}

// ---------------------------------------------------------------------------
extern "C" void kernel_launch(void* const* d_in, const int* in_sizes, int n_in,
                              void* d_out, int out_size) {
    const float* x     = (const float*)d_in[0];
    const float* A1    = (const float*)d_in[1];
    const float* A2    = (const float*)d_in[2];
    const float* A3    = (const float*)d_in[3];
    const float* A4    = (const float*)d_in[4];
    const float* B1    = (const float*)d_in[5];
    const float* B2    = (const float*)d_in[6];
    const float* C1    = (const float*)d_in[7];
    const float* C2    = (const float*)d_in[8];
    const float* omega = (const float*)d_in[9];
    float* out = (float*)d_out;

    compute_k_kernel<<<8, 32>>>(A1, A2, A3, A4, B1, B2, C1, C2);
    build_T_kernel<<<GROUPS, 256>>>();
    transpose_kernel<<<SEQ * BSZ / 32, 256>>>(x);
    gemm_kernel<<<dim3(GCOLS / 128, 1024 / 256, GROUPS), 512>>>();
    epilogue_kernel<<<SEQ * BSZ / 4, 512>>>(x, omega, out);
}

// round 9
// speedup vs baseline: 1.0793x; 1.0793x over previous
#include <cuda_runtime.h>
#include <cuda_fp16.h>
#include <math.h>
#include <stdint.h>

// ---------------------------------------------------------------------------
// TwoDimensionalSSM: out = silu( conv4dir(x, k) + x*omega )
// M_n is 2-level Toeplitz: M[(i,j),(u,v)] = T_n(i-u, j-v), T = 63x63 table.
// GEMM Out_n = M_n @ X_n^T with A fragments generated from the smem table.
// A-fragment dedup: T[i-u][j+8-(v+8)] = T[i-u][j-v] -> 7 unique LDS per u-step.
// ---------------------------------------------------------------------------

#define LSIDE  32
#define SEQ    1024
#define BSZ    32
#define EMBED  512
#define NSSM   32
#define KDIM   128
#define GROUPS 32
#define GCOLS  512
#define TROWS  63
#define TCOLSW 64          // padded row width
#define TSZ    (TROWS * TCOLSW)   // 4032 uint32 per group

// Static device scratch (allocation-free, graph-capturable)
__device__ float  g_kpart[2][KDIM][SEQ];                             // 1 MB
__device__ __align__(16) uint32_t g_Tp[(size_t)GROUPS * TSZ];        // 516 KB pair tables
__device__ __align__(16) __half g_X[(size_t)GROUPS * GCOLS * 1024];  // 32 MB  [n][c][s]
__device__ __align__(16) __half g_Outh[(size_t)GROUPS * 1024 * GCOLS]; // 32 MB [n][sp][c]

__device__ __forceinline__ float sigmoidf_(float v) { return 1.0f / (1.0f + expf(-v)); }

__device__ __forceinline__ uint32_t smem_u32(const void* p) {
    return (uint32_t)__cvta_generic_to_shared(p);
}
__device__ __forceinline__ void cp_async16(uint32_t dst, const void* src) {
    asm volatile("cp.async.cg.shared.global [%0], [%1], 16;" :: "r"(dst), "l"(src) : "memory");
}
__device__ __forceinline__ void cp_commit() {
    asm volatile("cp.async.commit_group;" ::: "memory");
}
__device__ __forceinline__ uint32_t lds32(uint32_t addr) {
    uint32_t v;
    asm volatile("ld.shared.b32 %0, [%1];" : "=r"(v) : "r"(addr));
    return v;
}
__device__ __forceinline__ void ldsm_x4(uint32_t* r, uint32_t addr) {
    asm volatile("ldmatrix.sync.aligned.m8n8.x4.shared.b16 {%0,%1,%2,%3}, [%4];"
                 : "=r"(r[0]), "=r"(r[1]), "=r"(r[2]), "=r"(r[3]) : "r"(addr));
}
__device__ __forceinline__ void mma16816(float* c, uint32_t a0, uint32_t a1, uint32_t a2,
                                         uint32_t a3, uint32_t b0, uint32_t b1) {
    asm volatile(
        "mma.sync.aligned.m16n8k16.row.col.f32.f16.f16.f32 "
        "{%0,%1,%2,%3}, {%4,%5,%6,%7}, {%8,%9}, {%0,%1,%2,%3};"
        : "+f"(c[0]), "+f"(c[1]), "+f"(c[2]), "+f"(c[3])
        : "r"(a0), "r"(a1), "r"(a2), "r"(a3), "r"(b0), "r"(b1));
}

// ---------------------------------------------------------------------------
// Kernel 1: 2-D SSM recurrence -> impulse response partials per (h, state n).
// ---------------------------------------------------------------------------
__global__ void compute_k_kernel(const float* __restrict__ A1p, const float* __restrict__ A2p,
                                 const float* __restrict__ A3p, const float* __restrict__ A4p,
                                 const float* __restrict__ B1p, const float* __restrict__ B2p,
                                 const float* __restrict__ C1p, const float* __restrict__ C2p) {
    int g = blockIdx.x * blockDim.x + threadIdx.x;
    if (g >= 2 * KDIM) return;
    int h = g >> 1, nn = g & 1;
    int idx = h * 2 + nn;
    float A1 = sigmoidf_(A1p[idx]);
    float A2 = sigmoidf_(A2p[idx]);
    float A3 = sigmoidf_(A3p[idx]);
    float A4 = sigmoidf_(A4p[idx]);
    float B1 = sigmoidf_(B1p[idx]);
    float B2 = sigmoidf_(B2p[idx]);
    const float scale = 0.70710678118654752f;
    float C1 = C1p[idx] * scale;
    float C2 = C2p[idx] * scale;

    float xh_up[LSIDE], xv_up[LSIDE];
#pragma unroll
    for (int j = 0; j < LSIDE; j++) { xh_up[j] = 0.0f; xv_up[j] = 0.0f; }

    float* kout = &g_kpart[nn][h][0];
    for (int i = 0; i < LSIDE; i++) {
        float xh_prev = 0.0f, xv_prev = 0.0f;
        for (int j = 0; j < LSIDE; j++) {
            float u = (i == 0 && j == 0) ? 1.0f : 0.0f;
            float xv_new  = A3 * xh_up[j] + A4 * xv_up[j] + B2 * u;
            float xv_left = (j == 0) ? 0.0f : xv_prev;
            float xh_new  = A1 * xh_prev + A2 * xv_left + B1 * u;
            kout[i * LSIDE + j] = C1 * xh_new + C2 * xv_new;
            xh_up[j] = xh_new; xv_up[j] = xv_new;
            xh_prev  = xh_new; xv_prev  = xv_new;
        }
    }
}

// ---------------------------------------------------------------------------
// Kernel 2: build Toeplitz pair tables.
//  Spair[da+31][p] = half2( T[da][32-p], T[da][31-p] )   (p = 32 - db)
// ---------------------------------------------------------------------------
__global__ __launch_bounds__(256) void build_T_kernel() {
    int n = blockIdx.x;
    __shared__ float sk[4][1024];
    int tid = threadIdx.x;
#pragma unroll
    for (int it = 0; it < 16; it++) {
        int idx = tid + it * 256;
        int d  = idx >> 10;
        int ab = idx & 1023;
        int a = ab >> 5, b = ab & 31;
        float v = g_kpart[0][d * NSSM + n][ab] + g_kpart[1][d * NSSM + n][ab];
        float f = 1.0f;
        if (!(a == 0 && b == 0)) {
            if (a == 0) f *= 2.0f;
            if (b == 0) f *= 2.0f;
        }
        sk[d][ab] = v * f;
    }
    __syncthreads();

    auto Tval = [&](int da, int db) -> float {
        if (db > 31 || db < -31) return 0.0f;
        int a = da < 0 ? -da : da;
        int b = db < 0 ? -db : db;
        int idx = a * 32 + b;
        float r = 0.0f;
        if (da >= 0 && db >= 0) r += sk[0][idx];
        if (da <= 0 && db >= 0) r += sk[1][idx];
        if (da >= 0 && db <= 0) r += sk[2][idx];
        if (da <= 0 && db <= 0) r += sk[3][idx];
        return r;
    };

#pragma unroll
    for (int t = 0; t < 16; t++) {
        int e = tid + t * 256;
        if (e < TSZ) {
            int da = (e >> 6) - 31;
            int p  = e & 63;
            __half2 h = __floats2half2_rn(Tval(da, 32 - p), Tval(da, 31 - p));
            g_Tp[(size_t)n * TSZ + e] = *(uint32_t*)&h;
        }
    }
}

// ---------------------------------------------------------------------------
// Kernel 3: gather/transpose x (S,B,E) fp32 -> g_X[n][c][s] fp16  (c=b*16+e/32)
// ---------------------------------------------------------------------------
__global__ __launch_bounds__(256) void transpose_kernel(const float* __restrict__ x) {
    __shared__ __half sm[32][520];
    int b  = blockIdx.x & 31;
    int s0 = (blockIdx.x >> 5) << 5;
    int t = threadIdx.x;
#pragma unroll
    for (int i = 0; i < 64; ++i) {
        int idx = t + (i << 8);
        int si = idx >> 9, e = idx & 511;
        sm[si][e] = __float2half_rn(x[(size_t)(s0 + si) * (BSZ * EMBED) + (size_t)b * EMBED + e]);
    }
    __syncthreads();
#pragma unroll
    for (int i = 0; i < 8; ++i) {
        int c2 = t + (i << 8);
        int pair = c2 >> 2, sj = (c2 & 3) << 3;
        int nn = pair & 31, r = pair >> 5;
        int e = (r << 5) + nn;
        __half tmp[8];
#pragma unroll
        for (int q = 0; q < 8; ++q) tmp[q] = sm[sj + q][e];
        *(uint4*)&g_X[((size_t)nn * GCOLS + b * 16 + r) * 1024 + s0 + sj] = *(uint4*)tmp;
    }
}

// ---------------------------------------------------------------------------
// Kernel 4: Toeplitz HMMA GEMM. CTA tile 128(M)x128(N), 256 threads,
// 8 warps (4M x 2N), warp tile 32x64. BK=64, 16 chunks, double-buffered B
// (2 x 16KB) + Spair table (16128B) = ~48KB.
// A: per u-step, 7 unique LDS.32 at 32B-spaced offsets serve all 16 A slots
// of both 16x16 fragments and both k-halves (Toeplitz diagonal dedup).
// ---------------------------------------------------------------------------
__global__ __launch_bounds__(256) void gemm_kernel() {
    __shared__ __align__(1024) __half bbuf[2 * 128 * 64];   // 32 KB B stages
    __shared__ __align__(16) uint32_t spair[TSZ];           // 16128 B table

    const int n  = blockIdx.z;
    const int m0 = blockIdx.y << 7;
    const int n0 = blockIdx.x << 7;
    const __half* Bg = g_X + ((size_t)n << 19);

    const int tid = threadIdx.x;
    const int wid = tid >> 5;
    const int lane = tid & 31;
    const int wm = wid & 3;          // 4 warps along M (32 rows each)
    const int wn = wid >> 2;         // 2 warps along N (64 cols each)

    const uint32_t sB = smem_u32(bbuf);
    const uint32_t sT = smem_u32(spair);
    const uint32_t B_STG = 16384;

    // table load (cp.async group 0)
    {
        const uint32_t* src = g_Tp + (size_t)n * TSZ;
#pragma unroll
        for (int i = 0; i < 4; ++i) {
            int id = tid + (i << 8);
            if (id < TSZ / 4) cp_async16(sT + id * 16, src + id * 4);
        }
        cp_commit();
    }

    auto load_chunk = [&](int c, int st) {
        int k0 = c << 6;
#pragma unroll
        for (int i = 0; i < 4; ++i) {            // B: 128 rows x 8 x 16B
            int id  = tid + (i << 8);            // 0..1023
            int row = id >> 3, k8 = id & 7;
            uint32_t sw = (uint32_t)(row * 128 + ((k8 << 4) ^ ((row & 7) << 4)));
            cp_async16(sB + (uint32_t)st * B_STG + sw,
                       Bg + (size_t)(n0 + row) * 1024 + k0 + (k8 << 3));
        }
        cp_commit();
    };

    load_chunk(0, 0);
    load_chunk(1, 1);

    float acc[2][8][4];
#pragma unroll
    for (int mi = 0; mi < 2; mi++)
#pragma unroll
        for (int nj = 0; nj < 8; nj++)
#pragma unroll
            for (int q = 0; q < 4; q++) acc[mi][nj][q] = 0.0f;

    // A base address (mi=0, rh=0 slot of the warp's 32-row strip):
    //   sp = m0 + wm*32 + (lane>>2);  p0 = &Spair[(i+31)*64 + (32-j) + (lane&3)*2]
    // All other fragment slots are at fixed byte offsets {-96..+96} from p0.
    uint32_t pA0;
    {
        int sp = m0 + wm * 32 + (lane >> 2);
        int i = sp >> 5, j = sp & 31;
        pA0 = sT + (uint32_t)(((i + 31) * 64 + (32 - j) + (lane & 3) * 2) * 4);
    }

    // B ldmatrix lane geometry
    const int bRow0 = wn * 64 + (lane & 7) + ((lane & 16) >> 1);   // + p*16
    const uint32_t bKsel = (uint32_t)((lane & 8) << 1);            // 0 or 16 bytes

    for (int c = 0; c < 16; ++c) {
        if (c < 14)       asm volatile("cp.async.wait_group 1;" ::: "memory");
        else              asm volatile("cp.async.wait_group 0;" ::: "memory");
        __syncthreads();

        uint32_t bS = sB + (uint32_t)(c & 1) * B_STG;

#pragma unroll
        for (int us = 0; us < 2; ++us) {
            int u = 2 * c + us;
            uint32_t ub = pA0 - (uint32_t)(u << 8);   // - u*64 entries*4B

            uint32_t t[7];
#pragma unroll
            for (int w = 0; w < 7; ++w) t[w] = lds32(ub + (uint32_t)((w - 3) * 32));

#pragma unroll
            for (int kh = 0; kh < 2; ++kh) {
                int ks = 2 * us + kh;
                uint32_t b[4][4];
#pragma unroll
                for (int p = 0; p < 4; p++) {
                    int row = bRow0 + p * 16;
                    uint32_t kb = (uint32_t)(ks << 5) + bKsel;
                    uint32_t addr = bS + (uint32_t)(row * 128)
                                  + (kb ^ (uint32_t)((row & 7) << 4));
                    ldsm_x4(b[p], addr);
                }
                int o = kh << 1;   // +2 t-slots for the k-hi half
#pragma unroll
                for (int nj = 0; nj < 8; nj++) {
                    int p = nj >> 1, e = (nj & 1) << 1;
                    // mi = 0: rows (j, j+8)
                    mma16816(acc[0][nj], t[3 + o], t[2 + o], t[4 + o], t[3 + o],
                             b[p][e], b[p][e + 1]);
                    // mi = 1: rows (j+16, j+24)
                    mma16816(acc[1][nj], t[1 + o], t[0 + o], t[2 + o], t[1 + o],
                             b[p][e], b[p][e + 1]);
                }
            }
        }
        __syncthreads();
        if (c + 2 < 16) load_chunk(c + 2, c & 1);
    }

    // writeout accumulators as fp16 pairs
    __half* C = g_Outh + ((size_t)n << 19);
    int colBase = n0 + wn * 64 + ((lane & 3) << 1);
    int rowBase = m0 + wm * 32 + (lane >> 2);
#pragma unroll
    for (int mi = 0; mi < 2; mi++) {
        int r = rowBase + mi * 16;
#pragma unroll
        for (int nj = 0; nj < 8; nj++) {
            int col = colBase + nj * 8;
            __half2 lo = __floats2half2_rn(acc[mi][nj][0], acc[mi][nj][1]);
            __half2 hi = __floats2half2_rn(acc[mi][nj][2], acc[mi][nj][3]);
            *(__half2*)&C[(size_t)r * GCOLS + col]       = lo;
            *(__half2*)&C[(size_t)(r + 8) * GCOLS + col] = hi;
        }
    }
}

// ---------------------------------------------------------------------------
// Kernel 5: un-gather Out(fp16) + residual x*omega + SiLU -> d_out fp32
// ---------------------------------------------------------------------------
__global__ __launch_bounds__(512) void epilogue_kernel(const float* __restrict__ x,
                                                       const float* __restrict__ omega,
                                                       float* __restrict__ out) {
    int blk = blockIdx.x;                 // 0..8191
    int b  = blk & 31;
    int s0 = (blk >> 5) << 2;             // 4 consecutive s
    __shared__ float sm[4][16 * 33 + 33];
    int tid = threadIdx.x;                // 512
#pragma unroll
    for (int pass = 0; pass < 2; pass++) {
        int sv = ((tid >> 8) << 1) + pass;   // covers 0..3 over 2 passes
        int q  = tid & 255;
        int nn = q >> 3, rr = (q & 7) << 1;
        __half2 v = *(const __half2*)&g_Outh[((size_t)nn << 19)
                                             + (size_t)(s0 + sv) * GCOLS + b * 16 + rr];
        sm[sv][rr * 33 + nn]       = __low2float(v);
        sm[sv][(rr + 1) * 33 + nn] = __high2float(v);
    }
    __syncthreads();
    float om = omega[tid];
    int sidx = (tid >> 5) * 33 + (tid & 31);
#pragma unroll
    for (int sv = 0; sv < 4; sv++) {
        size_t off = (size_t)(s0 + sv) * (BSZ * EMBED) + (size_t)b * EMBED + tid;
        float z = sm[sv][sidx] + x[off] * om;
        out[off] = z / (1.0f + expf(-z));
    }
}

// ---------------------------------------------------------------------------
extern "C" void kernel_launch(void* const* d_in, const int* in_sizes, int n_in,
                              void* d_out, int out_size) {
    const float* x     = (const float*)d_in[0];
    const float* A1    = (const float*)d_in[1];
    const float* A2    = (const float*)d_in[2];
    const float* A3    = (const float*)d_in[3];
    const float* A4    = (const float*)d_in[4];
    const float* B1    = (const float*)d_in[5];
    const float* B2    = (const float*)d_in[6];
    const float* C1    = (const float*)d_in[7];
    const float* C2    = (const float*)d_in[8];
    const float* omega = (const float*)d_in[9];
    float* out = (float*)d_out;

    compute_k_kernel<<<8, 32>>>(A1, A2, A3, A4, B1, B2, C1, C2);
    build_T_kernel<<<GROUPS, 256>>>();
    transpose_kernel<<<SEQ * BSZ / 32, 256>>>(x);
    gemm_kernel<<<dim3(GCOLS / 128, 1024 / 128, GROUPS), 256>>>();
    epilogue_kernel<<<SEQ * BSZ / 4, 512>>>(x, omega, out);
}

// round 10
// speedup vs baseline: 1.1772x; 1.0908x over previous
#include <cuda_runtime.h>
#include <cuda_fp16.h>
#include <math.h>
#include <stdint.h>

// ---------------------------------------------------------------------------
// TwoDimensionalSSM: out = silu( conv4dir(x, k) + x*omega )
// M_n is 2-level Toeplitz: M[(i,j),(u,v)] = T_n(i-u, j-v), T = 63x63 table.
// GEMM Out_n = M_n @ X_n^T with A fragments generated from the smem table.
// ---------------------------------------------------------------------------

#define LSIDE  32
#define SEQ    1024
#define BSZ    32
#define EMBED  512
#define NSSM   32
#define GROUPS 32
#define GCOLS  512
#define TROWS  63
#define TCOLSW 64
#define TSZ    (TROWS * TCOLSW)   // 4032 uint32 per group

// Static device scratch (allocation-free, graph-capturable)
__device__ __align__(16) uint32_t g_Tp[(size_t)GROUPS * TSZ];        // 516 KB pair tables
__device__ __align__(16) __half g_X[(size_t)GROUPS * GCOLS * 1024];  // 32 MB  [n][c][s]
__device__ __align__(16) __half g_Outh[(size_t)GROUPS * 1024 * GCOLS]; // 32 MB [n][sp][c]

__device__ __forceinline__ float sigmoidf_(float v) { return 1.0f / (1.0f + expf(-v)); }

__device__ __forceinline__ uint32_t smem_u32(const void* p) {
    return (uint32_t)__cvta_generic_to_shared(p);
}
__device__ __forceinline__ void cp_async16(uint32_t dst, const void* src) {
    asm volatile("cp.async.cg.shared.global [%0], [%1], 16;" :: "r"(dst), "l"(src) : "memory");
}
__device__ __forceinline__ void cp_commit() {
    asm volatile("cp.async.commit_group;" ::: "memory");
}
__device__ __forceinline__ uint32_t lds32(uint32_t addr) {
    uint32_t v;
    asm volatile("ld.shared.b32 %0, [%1];" : "=r"(v) : "r"(addr));
    return v;
}
__device__ __forceinline__ void ldsm_x4(uint32_t* r, uint32_t addr) {
    asm volatile("ldmatrix.sync.aligned.m8n8.x4.shared.b16 {%0,%1,%2,%3}, [%4];"
                 : "=r"(r[0]), "=r"(r[1]), "=r"(r[2]), "=r"(r[3]) : "r"(addr));
}
__device__ __forceinline__ void mma16816(float* c, uint32_t a0, uint32_t a1, uint32_t a2,
                                         uint32_t a3, uint32_t b0, uint32_t b1) {
    asm volatile(
        "mma.sync.aligned.m16n8k16.row.col.f32.f16.f16.f32 "
        "{%0,%1,%2,%3}, {%4,%5,%6,%7}, {%8,%9}, {%0,%1,%2,%3};"
        : "+f"(c[0]), "+f"(c[1]), "+f"(c[2]), "+f"(c[3])
        : "r"(a0), "r"(a1), "r"(a2), "r"(a3), "r"(b0), "r"(b1));
}

// ---------------------------------------------------------------------------
// Kernel 1 (fused): per group n, run the 8 (dir, state) SSM recurrences into
// smem, combine with boundary factors, emit the Toeplitz pair table:
//  Spair[da+31][p] = half2( T[da][32-p], T[da][31-p] )   (p = 32 - db)
// ---------------------------------------------------------------------------
__global__ __launch_bounds__(256) void build_T_kernel(
        const float* __restrict__ A1p, const float* __restrict__ A2p,
        const float* __restrict__ A3p, const float* __restrict__ A4p,
        const float* __restrict__ B1p, const float* __restrict__ B2p,
        const float* __restrict__ C1p, const float* __restrict__ C2p) {
    int n = blockIdx.x;
    __shared__ float sk2[8][1024];     // [nn*4+d][ab]; combined into [d][ab]
    int tid = threadIdx.x;

    if (tid < 8) {
        int d = tid >> 1, nn = tid & 1;
        int h = d * NSSM + n;
        int idx = h * 2 + nn;
        float A1 = sigmoidf_(A1p[idx]);
        float A2 = sigmoidf_(A2p[idx]);
        float A3 = sigmoidf_(A3p[idx]);
        float A4 = sigmoidf_(A4p[idx]);
        float B1 = sigmoidf_(B1p[idx]);
        float B2 = sigmoidf_(B2p[idx]);
        const float scale = 0.70710678118654752f;
        float C1 = C1p[idx] * scale;
        float C2 = C2p[idx] * scale;

        float xh_up[LSIDE], xv_up[LSIDE];
#pragma unroll
        for (int j = 0; j < LSIDE; j++) { xh_up[j] = 0.0f; xv_up[j] = 0.0f; }

        float* kout = &sk2[(nn << 2) + d][0];
        for (int i = 0; i < LSIDE; i++) {
            float xh_prev = 0.0f, xv_prev = 0.0f;
            for (int j = 0; j < LSIDE; j++) {
                float u = (i == 0 && j == 0) ? 1.0f : 0.0f;
                float xv_new  = A3 * xh_up[j] + A4 * xv_up[j] + B2 * u;
                float xv_left = (j == 0) ? 0.0f : xv_prev;
                float xh_new  = A1 * xh_prev + A2 * xv_left + B1 * u;
                kout[i * LSIDE + j] = C1 * xh_new + C2 * xv_new;
                xh_up[j] = xh_new; xv_up[j] = xv_new;
                xh_prev  = xh_new; xv_prev  = xv_new;
            }
        }
    }
    __syncthreads();

    // combine nn-partials + boundary factors, in place into sk2[d][ab]
#pragma unroll
    for (int it = 0; it < 16; it++) {
        int idx = tid + it * 256;          // 0..4095
        int d  = idx >> 10;
        int ab = idx & 1023;
        int a = ab >> 5, b = ab & 31;
        float v = sk2[d][ab] + sk2[4 + d][ab];
        float f = 1.0f;
        if (!(a == 0 && b == 0)) {
            if (a == 0) f *= 2.0f;
            if (b == 0) f *= 2.0f;
        }
        __syncwarp();
        sk2[d][ab] = v * f;
    }
    __syncthreads();

    auto Tval = [&](int da, int db) -> float {
        if (db > 31 || db < -31) return 0.0f;
        int a = da < 0 ? -da : da;
        int b = db < 0 ? -db : db;
        int idx = a * 32 + b;
        float r = 0.0f;
        if (da >= 0 && db >= 0) r += sk2[0][idx];
        if (da <= 0 && db >= 0) r += sk2[1][idx];
        if (da >= 0 && db <= 0) r += sk2[2][idx];
        if (da <= 0 && db <= 0) r += sk2[3][idx];
        return r;
    };

#pragma unroll
    for (int t = 0; t < 16; t++) {
        int e = tid + t * 256;
        if (e < TSZ) {
            int da = (e >> 6) - 31;
            int p  = e & 63;
            __half2 h = __floats2half2_rn(Tval(da, 32 - p), Tval(da, 31 - p));
            g_Tp[(size_t)n * TSZ + e] = *(uint32_t*)&h;
        }
    }
}

// ---------------------------------------------------------------------------
// Kernel 2: gather/transpose x (S,B,E) fp32 -> g_X[n][c][s] fp16  (c=b*16+e/32)
// ---------------------------------------------------------------------------
__global__ __launch_bounds__(256) void transpose_kernel(const float* __restrict__ x) {
    __shared__ __half sm[32][520];
    int b  = blockIdx.x & 31;
    int s0 = (blockIdx.x >> 5) << 5;
    int t = threadIdx.x;
#pragma unroll
    for (int i = 0; i < 64; ++i) {
        int idx = t + (i << 8);
        int si = idx >> 9, e = idx & 511;
        sm[si][e] = __float2half_rn(x[(size_t)(s0 + si) * (BSZ * EMBED) + (size_t)b * EMBED + e]);
    }
    __syncthreads();
#pragma unroll
    for (int i = 0; i < 8; ++i) {
        int c2 = t + (i << 8);
        int pair = c2 >> 2, sj = (c2 & 3) << 3;
        int nn = pair & 31, r = pair >> 5;
        int e = (r << 5) + nn;
        __half tmp[8];
#pragma unroll
        for (int q = 0; q < 8; ++q) tmp[q] = sm[sj + q][e];
        *(uint4*)&g_X[((size_t)nn * GCOLS + b * 16 + r) * 1024 + s0 + sj] = *(uint4*)tmp;
    }
}

// ---------------------------------------------------------------------------
// Kernel 3: Toeplitz HMMA GEMM. CTA tile 128(M)x64(N), 128 threads (4 warps,
// warp tile 32x64) -> ~5 CTAs/SM with INDEPENDENT 4-warp barriers.
// BK=64, 16 chunks, double-buffered B (2 x 8KB) + Spair table (16128B) = 32KB.
// A: per u-step, 7 unique LDS.32 serve all 16 A slots (Toeplitz dedup).
// ---------------------------------------------------------------------------
__global__ __launch_bounds__(128) void gemm_kernel() {
    __shared__ __align__(1024) __half bbuf[2 * 64 * 64];    // 16 KB B stages
    __shared__ __align__(16) uint32_t spair[TSZ];           // 16128 B table

    const int n  = blockIdx.z;
    const int m0 = blockIdx.y << 7;
    const int n0 = blockIdx.x << 6;
    const __half* Bg = g_X + ((size_t)n << 19);

    const int tid = threadIdx.x;
    const int wm = tid >> 5;         // 4 warps along M (32 rows each)
    const int lane = tid & 31;

    const uint32_t sB = smem_u32(bbuf);
    const uint32_t sT = smem_u32(spair);
    const uint32_t B_STG = 8192;

    // table load (cp.async group 0)
    {
        const uint32_t* src = g_Tp + (size_t)n * TSZ;
#pragma unroll
        for (int i = 0; i < 8; ++i) {
            int id = tid + (i << 7);
            if (id < TSZ / 4) cp_async16(sT + id * 16, src + id * 4);
        }
        cp_commit();
    }

    auto load_chunk = [&](int c, int st) {
        int k0 = c << 6;
#pragma unroll
        for (int i = 0; i < 4; ++i) {            // B: 64 rows x 8 x 16B
            int id  = tid + (i << 7);            // 0..511
            int row = id >> 3, k8 = id & 7;
            uint32_t sw = (uint32_t)(row * 128 + ((k8 << 4) ^ ((row & 7) << 4)));
            cp_async16(sB + (uint32_t)st * B_STG + sw,
                       Bg + (size_t)(n0 + row) * 1024 + k0 + (k8 << 3));
        }
        cp_commit();
    };

    load_chunk(0, 0);
    load_chunk(1, 1);

    float acc[2][8][4];
#pragma unroll
    for (int mi = 0; mi < 2; mi++)
#pragma unroll
        for (int nj = 0; nj < 8; nj++)
#pragma unroll
            for (int q = 0; q < 4; q++) acc[mi][nj][q] = 0.0f;

    // A base address (warp's 32-row strip); all fragment slots are at fixed
    // byte offsets {-96..+96} from pA0, minus u*256 per K-step.
    uint32_t pA0;
    {
        int sp = m0 + wm * 32 + (lane >> 2);
        int i = sp >> 5, j = sp & 31;
        pA0 = sT + (uint32_t)(((i + 31) * 64 + (32 - j) + (lane & 3) * 2) * 4);
    }

    // B ldmatrix lane geometry (rows 0..63 of the stage)
    const int bRow0 = (lane & 7) + ((lane & 16) >> 1);   // + p*16
    const uint32_t bKsel = (uint32_t)((lane & 8) << 1);  // 0 or 16 bytes

    for (int c = 0; c < 16; ++c) {
        if (c < 14)       asm volatile("cp.async.wait_group 1;" ::: "memory");
        else              asm volatile("cp.async.wait_group 0;" ::: "memory");
        __syncthreads();

        uint32_t bS = sB + (uint32_t)(c & 1) * B_STG;

#pragma unroll
        for (int us = 0; us < 2; ++us) {
            int u = 2 * c + us;
            uint32_t ub = pA0 - (uint32_t)(u << 8);

            uint32_t t[7];
#pragma unroll
            for (int w = 0; w < 7; ++w) t[w] = lds32(ub + (uint32_t)((w - 3) * 32));

#pragma unroll
            for (int kh = 0; kh < 2; ++kh) {
                int ks = 2 * us + kh;
                uint32_t b[4][4];
#pragma unroll
                for (int p = 0; p < 4; p++) {
                    int row = bRow0 + p * 16;
                    uint32_t kb = (uint32_t)(ks << 5) + bKsel;
                    uint32_t addr = bS + (uint32_t)(row * 128)
                                  + (kb ^ (uint32_t)((row & 7) << 4));
                    ldsm_x4(b[p], addr);
                }
                int o = kh << 1;
#pragma unroll
                for (int nj = 0; nj < 8; nj++) {
                    int p = nj >> 1, e = (nj & 1) << 1;
                    mma16816(acc[0][nj], t[3 + o], t[2 + o], t[4 + o], t[3 + o],
                             b[p][e], b[p][e + 1]);
                    mma16816(acc[1][nj], t[1 + o], t[0 + o], t[2 + o], t[1 + o],
                             b[p][e], b[p][e + 1]);
                }
            }
        }
        __syncthreads();
        if (c + 2 < 16) load_chunk(c + 2, c & 1);
    }

    // writeout accumulators as fp16 pairs
    __half* C = g_Outh + ((size_t)n << 19);
    int colBase = n0 + ((lane & 3) << 1);
    int rowBase = m0 + wm * 32 + (lane >> 2);
#pragma unroll
    for (int mi = 0; mi < 2; mi++) {
        int r = rowBase + mi * 16;
#pragma unroll
        for (int nj = 0; nj < 8; nj++) {
            int col = colBase + nj * 8;
            __half2 lo = __floats2half2_rn(acc[mi][nj][0], acc[mi][nj][1]);
            __half2 hi = __floats2half2_rn(acc[mi][nj][2], acc[mi][nj][3]);
            *(__half2*)&C[(size_t)r * GCOLS + col]       = lo;
            *(__half2*)&C[(size_t)(r + 8) * GCOLS + col] = hi;
        }
    }
}

// ---------------------------------------------------------------------------
// Kernel 4: un-gather Out(fp16) + residual x*omega + SiLU -> d_out fp32
// ---------------------------------------------------------------------------
__global__ __launch_bounds__(512) void epilogue_kernel(const float* __restrict__ x,
                                                       const float* __restrict__ omega,
                                                       float* __restrict__ out) {
    int blk = blockIdx.x;                 // 0..8191
    int b  = blk & 31;
    int s0 = (blk >> 5) << 2;             // 4 consecutive s
    __shared__ float sm[4][16 * 33 + 33];
    int tid = threadIdx.x;                // 512
#pragma unroll
    for (int pass = 0; pass < 2; pass++) {
        int sv = ((tid >> 8) << 1) + pass;
        int q  = tid & 255;
        int nn = q >> 3, rr = (q & 7) << 1;
        __half2 v = *(const __half2*)&g_Outh[((size_t)nn << 19)
                                             + (size_t)(s0 + sv) * GCOLS + b * 16 + rr];
        sm[sv][rr * 33 + nn]       = __low2float(v);
        sm[sv][(rr + 1) * 33 + nn] = __high2float(v);
    }
    __syncthreads();
    float om = omega[tid];
    int sidx = (tid >> 5) * 33 + (tid & 31);
#pragma unroll
    for (int sv = 0; sv < 4; sv++) {
        size_t off = (size_t)(s0 + sv) * (BSZ * EMBED) + (size_t)b * EMBED + tid;
        float z = sm[sv][sidx] + x[off] * om;
        out[off] = z / (1.0f + expf(-z));
    }
}

// ---------------------------------------------------------------------------
extern "C" void kernel_launch(void* const* d_in, const int* in_sizes, int n_in,
                              void* d_out, int out_size) {
    const float* x     = (const float*)d_in[0];
    const float* A1    = (const float*)d_in[1];
    const float* A2    = (const float*)d_in[2];
    const float* A3    = (const float*)d_in[3];
    const float* A4    = (const float*)d_in[4];
    const float* B1    = (const float*)d_in[5];
    const float* B2    = (const float*)d_in[6];
    const float* C1    = (const float*)d_in[7];
    const float* C2    = (const float*)d_in[8];
    const float* omega = (const float*)d_in[9];
    float* out = (float*)d_out;

    build_T_kernel<<<GROUPS, 256>>>(A1, A2, A3, A4, B1, B2, C1, C2);
    transpose_kernel<<<SEQ * BSZ / 32, 256>>>(x);
    gemm_kernel<<<dim3(GCOLS / 64, 1024 / 128, GROUPS), 128>>>();
    epilogue_kernel<<<SEQ * BSZ / 4, 512>>>(x, omega, out);
}

// round 12
// speedup vs baseline: 1.3721x; 1.1655x over previous
#include <cuda_runtime.h>
#include <cuda_fp16.h>
#include <math.h>
#include <stdint.h>

// ---------------------------------------------------------------------------
// TwoDimensionalSSM: out = silu( conv4dir(x, k) + x*omega )
// M_n is 2-level Toeplitz: M[(i,j),(u,v)] = T_n(i-u, j-v), T = 63x63 table.
// GEMM Out_n = M_n @ X_n^T with A fragments generated from the smem table.
// ---------------------------------------------------------------------------

#define LSIDE  32
#define SEQ    1024
#define BSZ    32
#define EMBED  512
#define NSSM   32
#define GROUPS 32
#define GCOLS  512
#define TROWS  63
#define TCOLSW 64
#define TSZ    (TROWS * TCOLSW)   // 4032 uint32 per group

// Static device scratch (allocation-free, graph-capturable)
__device__ __align__(16) uint32_t g_Tp[(size_t)GROUPS * TSZ];        // 516 KB pair tables
__device__ __align__(16) __half g_X[(size_t)GROUPS * GCOLS * 1024];  // 32 MB  [n][c][s]
__device__ __align__(16) __half g_Outh[(size_t)GROUPS * 1024 * GCOLS]; // 32 MB [n][sp][c]

__device__ __forceinline__ float sigmoidf_(float v) { return 1.0f / (1.0f + expf(-v)); }

__device__ __forceinline__ uint32_t smem_u32(const void* p) {
    return (uint32_t)__cvta_generic_to_shared(p);
}
__device__ __forceinline__ void cp_async16(uint32_t dst, const void* src) {
    asm volatile("cp.async.cg.shared.global [%0], [%1], 16;" :: "r"(dst), "l"(src) : "memory");
}
__device__ __forceinline__ void cp_commit() {
    asm volatile("cp.async.commit_group;" ::: "memory");
}
__device__ __forceinline__ uint32_t lds32(uint32_t addr) {
    uint32_t v;
    asm volatile("ld.shared.b32 %0, [%1];" : "=r"(v) : "r"(addr));
    return v;
}
__device__ __forceinline__ void ldsm_x4(uint32_t* r, uint32_t addr) {
    asm volatile("ldmatrix.sync.aligned.m8n8.x4.shared.b16 {%0,%1,%2,%3}, [%4];"
                 : "=r"(r[0]), "=r"(r[1]), "=r"(r[2]), "=r"(r[3]) : "r"(addr));
}
__device__ __forceinline__ void mma16816(float* c, uint32_t a0, uint32_t a1, uint32_t a2,
                                         uint32_t a3, uint32_t b0, uint32_t b1) {
    asm volatile(
        "mma.sync.aligned.m16n8k16.row.col.f32.f16.f16.f32 "
        "{%0,%1,%2,%3}, {%4,%5,%6,%7}, {%8,%9}, {%0,%1,%2,%3};"
        : "+f"(c[0]), "+f"(c[1]), "+f"(c[2]), "+f"(c[3])
        : "r"(a0), "r"(a1), "r"(a2), "r"(a3), "r"(b0), "r"(b1));
}

// ---------------------------------------------------------------------------
// Kernel 1 (fused): per group n, run the 8 (dir, state) SSM recurrences into
// smem, combine with boundary factors, emit the Toeplitz pair table:
//  Spair[da+31][p] = half2( T[da][32-p], T[da][31-p] )   (p = 32 - db)
// ---------------------------------------------------------------------------
__global__ __launch_bounds__(256) void build_T_kernel(
        const float* __restrict__ A1p, const float* __restrict__ A2p,
        const float* __restrict__ A3p, const float* __restrict__ A4p,
        const float* __restrict__ B1p, const float* __restrict__ B2p,
        const float* __restrict__ C1p, const float* __restrict__ C2p) {
    int n = blockIdx.x;
    __shared__ float sk2[8][1024];     // [nn*4+d][ab]; combined into [d][ab]
    int tid = threadIdx.x;

    if (tid < 8) {
        int d = tid >> 1, nn = tid & 1;
        int h = d * NSSM + n;
        int idx = h * 2 + nn;
        float A1 = sigmoidf_(A1p[idx]);
        float A2 = sigmoidf_(A2p[idx]);
        float A3 = sigmoidf_(A3p[idx]);
        float A4 = sigmoidf_(A4p[idx]);
        float B1 = sigmoidf_(B1p[idx]);
        float B2 = sigmoidf_(B2p[idx]);
        const float scale = 0.70710678118654752f;
        float C1 = C1p[idx] * scale;
        float C2 = C2p[idx] * scale;

        float xh_up[LSIDE], xv_up[LSIDE];
#pragma unroll
        for (int j = 0; j < LSIDE; j++) { xh_up[j] = 0.0f; xv_up[j] = 0.0f; }

        float* kout = &sk2[(nn << 2) + d][0];
        for (int i = 0; i < LSIDE; i++) {
            float xh_prev = 0.0f, xv_prev = 0.0f;
            for (int j = 0; j < LSIDE; j++) {
                float u = (i == 0 && j == 0) ? 1.0f : 0.0f;
                float xv_new  = A3 * xh_up[j] + A4 * xv_up[j] + B2 * u;
                float xv_left = (j == 0) ? 0.0f : xv_prev;
                float xh_new  = A1 * xh_prev + A2 * xv_left + B1 * u;
                kout[i * LSIDE + j] = C1 * xh_new + C2 * xv_new;
                xh_up[j] = xh_new; xv_up[j] = xv_new;
                xh_prev  = xh_new; xv_prev  = xv_new;
            }
        }
    }
    __syncthreads();

    // combine nn-partials + boundary factors, in place into sk2[d][ab]
#pragma unroll
    for (int it = 0; it < 16; it++) {
        int idx = tid + it * 256;          // 0..4095
        int d  = idx >> 10;
        int ab = idx & 1023;
        int a = ab >> 5, b = ab & 31;
        float v = sk2[d][ab] + sk2[4 + d][ab];
        float f = 1.0f;
        if (!(a == 0 && b == 0)) {
            if (a == 0) f *= 2.0f;
            if (b == 0) f *= 2.0f;
        }
        __syncwarp();
        sk2[d][ab] = v * f;
    }
    __syncthreads();

    auto Tval = [&](int da, int db) -> float {
        if (db > 31 || db < -31) return 0.0f;
        int a = da < 0 ? -da : da;
        int b = db < 0 ? -db : db;
        int idx = a * 32 + b;
        float r = 0.0f;
        if (da >= 0 && db >= 0) r += sk2[0][idx];
        if (da <= 0 && db >= 0) r += sk2[1][idx];
        if (da >= 0 && db <= 0) r += sk2[2][idx];
        if (da <= 0 && db <= 0) r += sk2[3][idx];
        return r;
    };

#pragma unroll
    for (int t = 0; t < 16; t++) {
        int e = tid + t * 256;
        if (e < TSZ) {
            int da = (e >> 6) - 31;
            int p  = e & 63;
            __half2 h = __floats2half2_rn(Tval(da, 32 - p), Tval(da, 31 - p));
            g_Tp[(size_t)n * TSZ + e] = *(uint32_t*)&h;
        }
    }
}

// ---------------------------------------------------------------------------
// Kernel 2: gather/transpose x (S,B,E) fp32 -> g_X[n][c][s] fp16  (c=b*16+e/32)
// float4 loads: 16 iterations x 16B per thread.
// ---------------------------------------------------------------------------
__global__ __launch_bounds__(256) void transpose_kernel(const float* __restrict__ x) {
    __shared__ __half sm[32][520];
    int b  = blockIdx.x & 31;
    int s0 = (blockIdx.x >> 5) << 5;
    int t = threadIdx.x;
#pragma unroll
    for (int i = 0; i < 16; ++i) {
        int idx4 = t + (i << 8);            // 0..4095 float4s
        int si = idx4 >> 7;                 // 128 float4 per 512-float row
        int e  = (idx4 & 127) << 2;
        float4 v = *(const float4*)&x[(size_t)(s0 + si) * (BSZ * EMBED)
                                      + (size_t)b * EMBED + e];
        __half2 h0 = __floats2half2_rn(v.x, v.y);
        __half2 h1 = __floats2half2_rn(v.z, v.w);
        *(__half2*)&sm[si][e]     = h0;
        *(__half2*)&sm[si][e + 2] = h1;
    }
    __syncthreads();
#pragma unroll
    for (int i = 0; i < 8; ++i) {
        int c2 = t + (i << 8);
        int pair = c2 >> 2, sj = (c2 & 3) << 3;
        int nn = pair & 31, r = pair >> 5;
        int e = (r << 5) + nn;
        __half tmp[8];
#pragma unroll
        for (int q = 0; q < 8; ++q) tmp[q] = sm[sj + q][e];
        *(uint4*)&g_X[((size_t)nn * GCOLS + b * 16 + r) * 1024 + s0 + sj] = *(uint4*)tmp;
    }
}

// ---------------------------------------------------------------------------
// Kernel 3: Toeplitz HMMA GEMM. CTA tile 128(M)x64(N), 128 threads (4 warps,
// warp tile 32x64) -> ~5 CTAs/SM with INDEPENDENT 4-warp barriers.
// BK=64, 16 chunks, double-buffered B (2 x 8KB) + Spair table (16128B) = 32KB.
// A: per u-step, 7 unique LDS.32 serve all 16 A slots (Toeplitz dedup).
// ---------------------------------------------------------------------------
__global__ __launch_bounds__(128) void gemm_kernel() {
    __shared__ __align__(1024) __half bbuf[2 * 64 * 64];    // 16 KB B stages
    __shared__ __align__(16) uint32_t spair[TSZ];           // 16128 B table

    const int n  = blockIdx.z;
    const int m0 = blockIdx.y << 7;
    const int n0 = blockIdx.x << 6;
    const __half* Bg = g_X + ((size_t)n << 19);

    const int tid = threadIdx.x;
    const int wm = tid >> 5;         // 4 warps along M (32 rows each)
    const int lane = tid & 31;

    const uint32_t sB = smem_u32(bbuf);
    const uint32_t sT = smem_u32(spair);
    const uint32_t B_STG = 8192;

    // table load (cp.async group 0)
    {
        const uint32_t* src = g_Tp + (size_t)n * TSZ;
#pragma unroll
        for (int i = 0; i < 8; ++i) {
            int id = tid + (i << 7);
            if (id < TSZ / 4) cp_async16(sT + id * 16, src + id * 4);
        }
        cp_commit();
    }

    auto load_chunk = [&](int c, int st) {
        int k0 = c << 6;
#pragma unroll
        for (int i = 0; i < 4; ++i) {            // B: 64 rows x 8 x 16B
            int id  = tid + (i << 7);            // 0..511
            int row = id >> 3, k8 = id & 7;
            uint32_t sw = (uint32_t)(row * 128 + ((k8 << 4) ^ ((row & 7) << 4)));
            cp_async16(sB + (uint32_t)st * B_STG + sw,
                       Bg + (size_t)(n0 + row) * 1024 + k0 + (k8 << 3));
        }
        cp_commit();
    };

    load_chunk(0, 0);
    load_chunk(1, 1);

    float acc[2][8][4];
#pragma unroll
    for (int mi = 0; mi < 2; mi++)
#pragma unroll
        for (int nj = 0; nj < 8; nj++)
#pragma unroll
            for (int q = 0; q < 4; q++) acc[mi][nj][q] = 0.0f;

    uint32_t pA0;
    {
        int sp = m0 + wm * 32 + (lane >> 2);
        int i = sp >> 5, j = sp & 31;
        pA0 = sT + (uint32_t)(((i + 31) * 64 + (32 - j) + (lane & 3) * 2) * 4);
    }

    const int bRow0 = (lane & 7) + ((lane & 16) >> 1);   // + p*16
    const uint32_t bKsel = (uint32_t)((lane & 8) << 1);  // 0 or 16 bytes

    for (int c = 0; c < 16; ++c) {
        if (c < 14)       asm volatile("cp.async.wait_group 1;" ::: "memory");
        else              asm volatile("cp.async.wait_group 0;" ::: "memory");
        __syncthreads();

        uint32_t bS = sB + (uint32_t)(c & 1) * B_STG;

#pragma unroll
        for (int us = 0; us < 2; ++us) {
            int u = 2 * c + us;
            uint32_t ub = pA0 - (uint32_t)(u << 8);

            uint32_t t[7];
#pragma unroll
            for (int w = 0; w < 7; ++w) t[w] = lds32(ub + (uint32_t)((w - 3) * 32));

#pragma unroll
            for (int kh = 0; kh < 2; ++kh) {
                int ks = 2 * us + kh;
                uint32_t b[4][4];
#pragma unroll
                for (int p = 0; p < 4; p++) {
                    int row = bRow0 + p * 16;
                    uint32_t kb = (uint32_t)(ks << 5) + bKsel;
                    uint32_t addr = bS + (uint32_t)(row * 128)
                                  + (kb ^ (uint32_t)((row & 7) << 4));
                    ldsm_x4(b[p], addr);
                }
                int o = kh << 1;
#pragma unroll
                for (int nj = 0; nj < 8; nj++) {
                    int p = nj >> 1, e = (nj & 1) << 1;
                    mma16816(acc[0][nj], t[3 + o], t[2 + o], t[4 + o], t[3 + o],
                             b[p][e], b[p][e + 1]);
                    mma16816(acc[1][nj], t[1 + o], t[0 + o], t[2 + o], t[1 + o],
                             b[p][e], b[p][e + 1]);
                }
            }
        }
        __syncthreads();
        if (c + 2 < 16) load_chunk(c + 2, c & 1);
    }

    // writeout accumulators as fp16 pairs
    __half* C = g_Outh + ((size_t)n << 19);
    int colBase = n0 + ((lane & 3) << 1);
    int rowBase = m0 + wm * 32 + (lane >> 2);
#pragma unroll
    for (int mi = 0; mi < 2; mi++) {
        int r = rowBase + mi * 16;
#pragma unroll
        for (int nj = 0; nj < 8; nj++) {
            int col = colBase + nj * 8;
            __half2 lo = __floats2half2_rn(acc[mi][nj][0], acc[mi][nj][1]);
            __half2 hi = __floats2half2_rn(acc[mi][nj][2], acc[mi][nj][3]);
            *(__half2*)&C[(size_t)r * GCOLS + col]       = lo;
            *(__half2*)&C[(size_t)(r + 8) * GCOLS + col] = hi;
        }
    }
}

// ---------------------------------------------------------------------------
// Kernel 4: un-gather Out(fp16) + residual x*omega + SiLU -> d_out fp32
// 8 sequence positions per block, uint4 gather loads, fast exp.
// ---------------------------------------------------------------------------
__global__ __launch_bounds__(512) void epilogue_kernel(const float* __restrict__ x,
                                                       const float* __restrict__ omega,
                                                       float* __restrict__ out) {
    int blk = blockIdx.x;                 // 0..4095
    int b  = blk & 31;
    int s0 = (blk >> 5) << 3;             // 8 consecutive s
    __shared__ float sm[8][16 * 33 + 16];
    int tid = threadIdx.x;                // 512

    // phase 1: one uint4 (8 halves = 8 r-values) per thread
    {
        int sv = tid >> 6;                // 0..7
        int q  = tid & 63;
        int nn = q >> 1;                  // 0..31
        int r0 = (q & 1) << 3;            // 0 or 8
        uint4 v = *(const uint4*)&g_Outh[((size_t)nn << 19)
                                         + (size_t)(s0 + sv) * GCOLS + b * 16 + r0];
        const __half* hv = (const __half*)&v;
#pragma unroll
        for (int k = 0; k < 8; ++k)
            sm[sv][(r0 + k) * 33 + nn] = __half2float(hv[k]);
    }
    __syncthreads();

    float om = omega[tid];
    int sidx = (tid >> 5) * 33 + (tid & 31);
#pragma unroll
    for (int sv = 0; sv < 8; sv++) {
        size_t off = (size_t)(s0 + sv) * (BSZ * EMBED) + (size_t)b * EMBED + tid;
        float z = fmaf(x[off], om, sm[sv][sidx]);
        out[off] = __fdividef(z, 1.0f + __expf(-z));
    }
}

// ---------------------------------------------------------------------------
extern "C" void kernel_launch(void* const* d_in, const int* in_sizes, int n_in,
                              void* d_out, int out_size) {
    const float* x     = (const float*)d_in[0];
    const float* A1    = (const float*)d_in[1];
    const float* A2    = (const float*)d_in[2];
    const float* A3    = (const float*)d_in[3];
    const float* A4    = (const float*)d_in[4];
    const float* B1    = (const float*)d_in[5];
    const float* B2    = (const float*)d_in[6];
    const float* C1    = (const float*)d_in[7];
    const float* C2    = (const float*)d_in[8];
    const float* omega = (const float*)d_in[9];
    float* out = (float*)d_out;

    build_T_kernel<<<GROUPS, 256>>>(A1, A2, A3, A4, B1, B2, C1, C2);
    transpose_kernel<<<SEQ * BSZ / 32, 256>>>(x);
    gemm_kernel<<<dim3(GCOLS / 64, 1024 / 128, GROUPS), 128>>>();
    epilogue_kernel<<<SEQ * BSZ / 8, 512>>>(x, omega, out);
}

// round 13
// speedup vs baseline: 1.4088x; 1.0267x over previous
#include <cuda_runtime.h>
#include <cuda_fp16.h>
#include <math.h>
#include <stdint.h>

// ---------------------------------------------------------------------------
// TwoDimensionalSSM: out = silu( conv4dir(x, k) + x*omega )
// M_n is 2-level Toeplitz: M[(i,j),(u,v)] = T_n(i-u, j-v), T = 63x63 table.
// GEMM Out_n = M_n @ X_n^T with A fragments generated from the smem table.
// ---------------------------------------------------------------------------

#define LSIDE  32
#define SEQ    1024
#define BSZ    32
#define EMBED  512
#define NSSM   32
#define GROUPS 32
#define GCOLS  512
#define TROWS  63
#define TCOLSW 64
#define TSZ    (TROWS * TCOLSW)   // 4032 uint32 per group

// Static device scratch (allocation-free, graph-capturable)
__device__ __align__(16) uint32_t g_Tp[(size_t)GROUPS * TSZ];        // 516 KB pair tables
__device__ __align__(16) __half g_X[(size_t)GROUPS * GCOLS * 1024];  // 32 MB  [n][c][s]
__device__ __align__(16) __half g_Outh[(size_t)GROUPS * 1024 * GCOLS]; // 32 MB [n][sp][c]

__device__ __forceinline__ float sigmoidf_(float v) { return 1.0f / (1.0f + expf(-v)); }

__device__ __forceinline__ uint32_t smem_u32(const void* p) {
    return (uint32_t)__cvta_generic_to_shared(p);
}
__device__ __forceinline__ void cp_async16(uint32_t dst, const void* src) {
    asm volatile("cp.async.cg.shared.global [%0], [%1], 16;" :: "r"(dst), "l"(src) : "memory");
}
__device__ __forceinline__ void cp_commit() {
    asm volatile("cp.async.commit_group;" ::: "memory");
}
__device__ __forceinline__ uint32_t lds32(uint32_t addr) {
    uint32_t v;
    asm volatile("ld.shared.b32 %0, [%1];" : "=r"(v) : "r"(addr));
    return v;
}
__device__ __forceinline__ void ldsm_x4(uint32_t* r, uint32_t addr) {
    asm volatile("ldmatrix.sync.aligned.m8n8.x4.shared.b16 {%0,%1,%2,%3}, [%4];"
                 : "=r"(r[0]), "=r"(r[1]), "=r"(r[2]), "=r"(r[3]) : "r"(addr));
}
__device__ __forceinline__ void mma16816(float* c, uint32_t a0, uint32_t a1, uint32_t a2,
                                         uint32_t a3, uint32_t b0, uint32_t b1) {
    asm volatile(
        "mma.sync.aligned.m16n8k16.row.col.f32.f16.f16.f32 "
        "{%0,%1,%2,%3}, {%4,%5,%6,%7}, {%8,%9}, {%0,%1,%2,%3};"
        : "+f"(c[0]), "+f"(c[1]), "+f"(c[2]), "+f"(c[3])
        : "r"(a0), "r"(a1), "r"(a2), "r"(a3), "r"(b0), "r"(b1));
}

// ---------------------------------------------------------------------------
// Kernel 1 (fused): per group n, run the 8 (dir, state) SSM recurrences into
// smem, combine with boundary factors, emit the Toeplitz pair table:
//  Spair[da+31][p] = half2( T[da][32-p], T[da][31-p] )   (p = 32 - db)
// ---------------------------------------------------------------------------
__global__ __launch_bounds__(256) void build_T_kernel(
        const float* __restrict__ A1p, const float* __restrict__ A2p,
        const float* __restrict__ A3p, const float* __restrict__ A4p,
        const float* __restrict__ B1p, const float* __restrict__ B2p,
        const float* __restrict__ C1p, const float* __restrict__ C2p) {
    int n = blockIdx.x;
    __shared__ float sk2[8][1024];     // [nn*4+d][ab]; combined into [d][ab]
    int tid = threadIdx.x;

    if (tid < 8) {
        int d = tid >> 1, nn = tid & 1;
        int h = d * NSSM + n;
        int idx = h * 2 + nn;
        float A1 = sigmoidf_(A1p[idx]);
        float A2 = sigmoidf_(A2p[idx]);
        float A3 = sigmoidf_(A3p[idx]);
        float A4 = sigmoidf_(A4p[idx]);
        float B1 = sigmoidf_(B1p[idx]);
        float B2 = sigmoidf_(B2p[idx]);
        const float scale = 0.70710678118654752f;
        float C1 = C1p[idx] * scale;
        float C2 = C2p[idx] * scale;

        float xh_up[LSIDE], xv_up[LSIDE];
#pragma unroll
        for (int j = 0; j < LSIDE; j++) { xh_up[j] = 0.0f; xv_up[j] = 0.0f; }

        float* kout = &sk2[(nn << 2) + d][0];
        for (int i = 0; i < LSIDE; i++) {
            float xh_prev = 0.0f, xv_prev = 0.0f;
#pragma unroll
            for (int j = 0; j < LSIDE; j++) {     // unrolled: keep arrays in regs
                float u = (i == 0 && j == 0) ? 1.0f : 0.0f;
                float xv_new  = A3 * xh_up[j] + A4 * xv_up[j] + B2 * u;
                float xv_left = (j == 0) ? 0.0f : xv_prev;
                float xh_new  = A1 * xh_prev + A2 * xv_left + B1 * u;
                kout[i * LSIDE + j] = C1 * xh_new + C2 * xv_new;
                xh_up[j] = xh_new; xv_up[j] = xv_new;
                xh_prev  = xh_new; xv_prev  = xv_new;
            }
        }
    }
    __syncthreads();

    // combine nn-partials + boundary factors, in place into sk2[d][ab]
#pragma unroll
    for (int it = 0; it < 16; it++) {
        int idx = tid + it * 256;          // 0..4095
        int d  = idx >> 10;
        int ab = idx & 1023;
        int a = ab >> 5, b = ab & 31;
        float v = sk2[d][ab] + sk2[4 + d][ab];
        float f = 1.0f;
        if (!(a == 0 && b == 0)) {
            if (a == 0) f *= 2.0f;
            if (b == 0) f *= 2.0f;
        }
        __syncwarp();
        sk2[d][ab] = v * f;
    }
    __syncthreads();

    auto Tval = [&](int da, int db) -> float {
        if (db > 31 || db < -31) return 0.0f;
        int a = da < 0 ? -da : da;
        int b = db < 0 ? -db : db;
        int idx = a * 32 + b;
        float r = 0.0f;
        if (da >= 0 && db >= 0) r += sk2[0][idx];
        if (da <= 0 && db >= 0) r += sk2[1][idx];
        if (da >= 0 && db <= 0) r += sk2[2][idx];
        if (da <= 0 && db <= 0) r += sk2[3][idx];
        return r;
    };

#pragma unroll
    for (int t = 0; t < 16; t++) {
        int e = tid + t * 256;
        if (e < TSZ) {
            int da = (e >> 6) - 31;
            int p  = e & 63;
            __half2 h = __floats2half2_rn(Tval(da, 32 - p), Tval(da, 31 - p));
            g_Tp[(size_t)n * TSZ + e] = *(uint32_t*)&h;
        }
    }
}

// ---------------------------------------------------------------------------
// Kernel 2: gather/transpose x (S,B,E) fp32 -> g_X[n][c][s] fp16  (c=b*16+e/32)
// float4 loads: 16 iterations x 16B per thread.
// ---------------------------------------------------------------------------
__global__ __launch_bounds__(256) void transpose_kernel(const float* __restrict__ x) {
    __shared__ __half sm[32][520];
    int b  = blockIdx.x & 31;
    int s0 = (blockIdx.x >> 5) << 5;
    int t = threadIdx.x;
#pragma unroll
    for (int i = 0; i < 16; ++i) {
        int idx4 = t + (i << 8);            // 0..4095 float4s
        int si = idx4 >> 7;                 // 128 float4 per 512-float row
        int e  = (idx4 & 127) << 2;
        float4 v = *(const float4*)&x[(size_t)(s0 + si) * (BSZ * EMBED)
                                      + (size_t)b * EMBED + e];
        __half2 h0 = __floats2half2_rn(v.x, v.y);
        __half2 h1 = __floats2half2_rn(v.z, v.w);
        *(__half2*)&sm[si][e]     = h0;
        *(__half2*)&sm[si][e + 2] = h1;
    }
    __syncthreads();
#pragma unroll
    for (int i = 0; i < 8; ++i) {
        int c2 = t + (i << 8);
        int pair = c2 >> 2, sj = (c2 & 3) << 3;
        int nn = pair & 31, r = pair >> 5;
        int e = (r << 5) + nn;
        __half tmp[8];
#pragma unroll
        for (int q = 0; q < 8; ++q) tmp[q] = sm[sj + q][e];
        *(uint4*)&g_X[((size_t)nn * GCOLS + b * 16 + r) * 1024 + s0 + sj] = *(uint4*)tmp;
    }
}

// ---------------------------------------------------------------------------
// Kernel 3: Toeplitz HMMA GEMM. CTA tile 128(M)x64(N), 128 threads (4 warps,
// warp tile 32x64). 3-stage cp.async pipeline, ONE __syncthreads per chunk:
//   wait(stage c) -> sync -> issue load c+2 into stage freed last iter -> mma.
// Smem: 3 x 8KB B stages + 16128B table = ~40KB -> 5 CTAs/SM.
// A: per u-step, 7 unique LDS.32 serve all 16 A slots (Toeplitz dedup).
// ---------------------------------------------------------------------------
__global__ __launch_bounds__(128) void gemm_kernel() {
    __shared__ __align__(1024) __half bbuf[3 * 64 * 64];    // 24 KB B stages
    __shared__ __align__(16) uint32_t spair[TSZ];           // 16128 B table

    const int n  = blockIdx.z;
    const int m0 = blockIdx.y << 7;
    const int n0 = blockIdx.x << 6;
    const __half* Bg = g_X + ((size_t)n << 19);

    const int tid = threadIdx.x;
    const int wm = tid >> 5;         // 4 warps along M (32 rows each)
    const int lane = tid & 31;

    const uint32_t sB = smem_u32(bbuf);
    const uint32_t sT = smem_u32(spair);
    const uint32_t B_STG = 8192;

    // table load (cp.async group 0)
    {
        const uint32_t* src = g_Tp + (size_t)n * TSZ;
#pragma unroll
        for (int i = 0; i < 8; ++i) {
            int id = tid + (i << 7);
            if (id < TSZ / 4) cp_async16(sT + id * 16, src + id * 4);
        }
        cp_commit();
    }

    auto load_chunk = [&](int c, int st) {
        int k0 = c << 6;
#pragma unroll
        for (int i = 0; i < 4; ++i) {            // B: 64 rows x 8 x 16B
            int id  = tid + (i << 7);            // 0..511
            int row = id >> 3, k8 = id & 7;
            uint32_t sw = (uint32_t)(row * 128 + ((k8 << 4) ^ ((row & 7) << 4)));
            cp_async16(sB + (uint32_t)st * B_STG + sw,
                       Bg + (size_t)(n0 + row) * 1024 + k0 + (k8 << 3));
        }
        cp_commit();
    };

    load_chunk(0, 0);
    load_chunk(1, 1);

    float acc[2][8][4];
#pragma unroll
    for (int mi = 0; mi < 2; mi++)
#pragma unroll
        for (int nj = 0; nj < 8; nj++)
#pragma unroll
            for (int q = 0; q < 4; q++) acc[mi][nj][q] = 0.0f;

    uint32_t pA0;
    {
        int sp = m0 + wm * 32 + (lane >> 2);
        int i = sp >> 5, j = sp & 31;
        pA0 = sT + (uint32_t)(((i + 31) * 64 + (32 - j) + (lane & 3) * 2) * 4);
    }

    const int bRow0 = (lane & 7) + ((lane & 16) >> 1);   // + p*16
    const uint32_t bKsel = (uint32_t)((lane & 8) << 1);  // 0 or 16 bytes

    int st = 0;                       // stage of chunk c
    for (int c = 0; c < 16; ++c) {
        if (c < 15) asm volatile("cp.async.wait_group 1;" ::: "memory");
        else        asm volatile("cp.async.wait_group 0;" ::: "memory");
        __syncthreads();

        // stage freed by last iteration's compute = (c+2) % 3
        if (c + 2 < 16) {
            int fs = st - 1; if (fs < 0) fs = 2;
            load_chunk(c + 2, fs);
        }

        uint32_t bS = sB + (uint32_t)st * B_STG;

#pragma unroll
        for (int us = 0; us < 2; ++us) {
            int u = 2 * c + us;
            uint32_t ub = pA0 - (uint32_t)(u << 8);

            uint32_t t[7];
#pragma unroll
            for (int w = 0; w < 7; ++w) t[w] = lds32(ub + (uint32_t)((w - 3) * 32));

#pragma unroll
            for (int kh = 0; kh < 2; ++kh) {
                int ks = 2 * us + kh;
                uint32_t b[4][4];
#pragma unroll
                for (int p = 0; p < 4; p++) {
                    int row = bRow0 + p * 16;
                    uint32_t kb = (uint32_t)(ks << 5) + bKsel;
                    uint32_t addr = bS + (uint32_t)(row * 128)
                                  + (kb ^ (uint32_t)((row & 7) << 4));
                    ldsm_x4(b[p], addr);
                }
                int o = kh << 1;
#pragma unroll
                for (int nj = 0; nj < 8; nj++) {
                    int p = nj >> 1, e = (nj & 1) << 1;
                    mma16816(acc[0][nj], t[3 + o], t[2 + o], t[4 + o], t[3 + o],
                             b[p][e], b[p][e + 1]);
                    mma16816(acc[1][nj], t[1 + o], t[0 + o], t[2 + o], t[1 + o],
                             b[p][e], b[p][e + 1]);
                }
            }
        }
        if (++st == 3) st = 0;
    }

    // writeout accumulators as fp16 pairs
    __half* C = g_Outh + ((size_t)n << 19);
    int colBase = n0 + ((lane & 3) << 1);
    int rowBase = m0 + wm * 32 + (lane >> 2);
#pragma unroll
    for (int mi = 0; mi < 2; mi++) {
        int r = rowBase + mi * 16;
#pragma unroll
        for (int nj = 0; nj < 8; nj++) {
            int col = colBase + nj * 8;
            __half2 lo = __floats2half2_rn(acc[mi][nj][0], acc[mi][nj][1]);
            __half2 hi = __floats2half2_rn(acc[mi][nj][2], acc[mi][nj][3]);
            *(__half2*)&C[(size_t)r * GCOLS + col]       = lo;
            *(__half2*)&C[(size_t)(r + 8) * GCOLS + col] = hi;
        }
    }
}

// ---------------------------------------------------------------------------
// Kernel 4: un-gather Out(fp16) + residual x*omega + SiLU -> d_out fp32
// 8 sequence positions per block, uint4 gather loads, fast exp.
// ---------------------------------------------------------------------------
__global__ __launch_bounds__(512) void epilogue_kernel(const float* __restrict__ x,
                                                       const float* __restrict__ omega,
                                                       float* __restrict__ out) {
    int blk = blockIdx.x;                 // 0..4095
    int b  = blk & 31;
    int s0 = (blk >> 5) << 3;             // 8 consecutive s
    __shared__ float sm[8][16 * 33 + 16];
    int tid = threadIdx.x;                // 512

    // phase 1: one uint4 (8 halves = 8 r-values) per thread
    {
        int sv = tid >> 6;                // 0..7
        int q  = tid & 63;
        int nn = q >> 1;                  // 0..31
        int r0 = (q & 1) << 3;            // 0 or 8
        uint4 v = *(const uint4*)&g_Outh[((size_t)nn << 19)
                                         + (size_t)(s0 + sv) * GCOLS + b * 16 + r0];
        const __half* hv = (const __half*)&v;
#pragma unroll
        for (int k = 0; k < 8; ++k)
            sm[sv][(r0 + k) * 33 + nn] = __half2float(hv[k]);
    }
    __syncthreads();

    float om = omega[tid];
    int sidx = (tid >> 5) * 33 + (tid & 31);
#pragma unroll
    for (int sv = 0; sv < 8; sv++) {
        size_t off = (size_t)(s0 + sv) * (BSZ * EMBED) + (size_t)b * EMBED + tid;
        float z = fmaf(x[off], om, sm[sv][sidx]);
        out[off] = __fdividef(z, 1.0f + __expf(-z));
    }
}

// ---------------------------------------------------------------------------
extern "C" void kernel_launch(void* const* d_in, const int* in_sizes, int n_in,
                              void* d_out, int out_size) {
    const float* x     = (const float*)d_in[0];
    const float* A1    = (const float*)d_in[1];
    const float* A2    = (const float*)d_in[2];
    const float* A3    = (const float*)d_in[3];
    const float* A4    = (const float*)d_in[4];
    const float* B1    = (const float*)d_in[5];
    const float* B2    = (const float*)d_in[6];
    const float* C1    = (const float*)d_in[7];
    const float* C2    = (const float*)d_in[8];
    const float* omega = (const float*)d_in[9];
    float* out = (float*)d_out;

    build_T_kernel<<<GROUPS, 256>>>(A1, A2, A3, A4, B1, B2, C1, C2);
    transpose_kernel<<<SEQ * BSZ / 32, 256>>>(x);
    gemm_kernel<<<dim3(GCOLS / 64, 1024 / 128, GROUPS), 128>>>();
    epilogue_kernel<<<SEQ * BSZ / 8, 512>>>(x, omega, out);
}

// round 16
// speedup vs baseline: 1.4845x; 1.0538x over previous
#include <cuda_runtime.h>
#include <cuda_fp16.h>
#include <math.h>
#include <stdint.h>

// ---------------------------------------------------------------------------
// TwoDimensionalSSM: out = silu( conv4dir(x, k) + x*omega )
// M_n is 2-level Toeplitz: M[(i,j),(u,v)] = T_n(i-u, j-v), T = 63x63 table.
// Persistent Toeplitz HMMA GEMM + fused prep + vectorized epilogue.
// ---------------------------------------------------------------------------

#define LSIDE  32
#define SEQ    1024
#define BSZ    32
#define EMBED  512
#define NSSM   32
#define GROUPS 32
#define GCOLS  512
#define TROWS  63
#define TCOLSW 64
#define TSZ    (TROWS * TCOLSW)   // 4032 uint32 per group

#define TRB 1024                   // transpose blocks = (SEQ/32) * BSZ = 32*32

// Static device scratch (allocation-free, graph-capturable)
__device__ __align__(16) uint32_t g_Tp[(size_t)GROUPS * TSZ];        // 516 KB pair tables
__device__ __align__(16) __half g_X[(size_t)GROUPS * GCOLS * 1024];  // 32 MB  [n][c][s]
__device__ __align__(16) __half g_Outh[(size_t)GROUPS * 1024 * GCOLS]; // 32 MB [n][sp][c]

__device__ __forceinline__ float sigmoidf_(float v) { return 1.0f / (1.0f + expf(-v)); }

__device__ __forceinline__ uint32_t smem_u32(const void* p) {
    return (uint32_t)__cvta_generic_to_shared(p);
}
__device__ __forceinline__ void cp_async16(uint32_t dst, const void* src) {
    asm volatile("cp.async.cg.shared.global [%0], [%1], 16;" :: "r"(dst), "l"(src) : "memory");
}
__device__ __forceinline__ void cp_commit() {
    asm volatile("cp.async.commit_group;" ::: "memory");
}
__device__ __forceinline__ uint32_t lds32(uint32_t addr) {
    uint32_t v;
    asm volatile("ld.shared.b32 %0, [%1];" : "=r"(v) : "r"(addr));
    return v;
}
__device__ __forceinline__ void ldsm_x4(uint32_t* r, uint32_t addr) {
    asm volatile("ldmatrix.sync.aligned.m8n8.x4.shared.b16 {%0,%1,%2,%3}, [%4];"
                 : "=r"(r[0]), "=r"(r[1]), "=r"(r[2]), "=r"(r[3]) : "r"(addr));
}
__device__ __forceinline__ void mma16816(float* c, uint32_t a0, uint32_t a1, uint32_t a2,
                                         uint32_t a3, uint32_t b0, uint32_t b1) {
    asm volatile(
        "mma.sync.aligned.m16n8k16.row.col.f32.f16.f16.f32 "
        "{%0,%1,%2,%3}, {%4,%5,%6,%7}, {%8,%9}, {%0,%1,%2,%3};"
        : "+f"(c[0]), "+f"(c[1]), "+f"(c[2]), "+f"(c[3])
        : "r"(a0), "r"(a1), "r"(a2), "r"(a3), "r"(b0), "r"(b1));
}

// ---------------------------------------------------------------------------
// Kernel 1 (fused prep): blocks [0, TRB) transpose x -> g_X; blocks
// [TRB, TRB+32) build the Toeplitz pair tables (hides under transpose).
// ---------------------------------------------------------------------------
__global__ __launch_bounds__(256) void prep_kernel(
        const float* __restrict__ x,
        const float* __restrict__ A1p, const float* __restrict__ A2p,
        const float* __restrict__ A3p, const float* __restrict__ A4p,
        const float* __restrict__ B1p, const float* __restrict__ B2p,
        const float* __restrict__ C1p, const float* __restrict__ C2p) {
    __shared__ __align__(16) char smraw[33664];
    int tid = threadIdx.x;

    if (blockIdx.x < TRB) {
        // ---- transpose: x (S,B,E) fp32 -> g_X[n][c][s] fp16, c=b*16+e/32 ----
        __half (*sm)[520] = (__half(*)[520])smraw;
        int b  = blockIdx.x & 31;
        int s0 = (blockIdx.x >> 5) << 5;
#pragma unroll
        for (int i = 0; i < 16; ++i) {
            int idx4 = tid + (i << 8);
            int si = idx4 >> 7;
            int e  = (idx4 & 127) << 2;
            float4 v = *(const float4*)&x[(size_t)(s0 + si) * (BSZ * EMBED)
                                          + (size_t)b * EMBED + e];
            *(__half2*)&sm[si][e]     = __floats2half2_rn(v.x, v.y);
            *(__half2*)&sm[si][e + 2] = __floats2half2_rn(v.z, v.w);
        }
        __syncthreads();
#pragma unroll
        for (int i = 0; i < 8; ++i) {
            int c2 = tid + (i << 8);
            int pair = c2 >> 2, sj = (c2 & 3) << 3;
            int nn = pair & 31, r = pair >> 5;
            int e = (r << 5) + nn;
            __half tmp[8];
#pragma unroll
            for (int q = 0; q < 8; ++q) tmp[q] = sm[sj + q][e];
            *(uint4*)&g_X[((size_t)nn * GCOLS + b * 16 + r) * 1024 + s0 + sj] = *(uint4*)tmp;
        }
        return;
    }

    // ---- build_T for group n ----
    int n = blockIdx.x - TRB;
    float (*sk2)[1024] = (float(*)[1024])smraw;

    if (tid < 8) {
        int d = tid >> 1, nn = tid & 1;
        int h = d * NSSM + n;
        int idx = h * 2 + nn;
        float A1 = sigmoidf_(A1p[idx]);
        float A2 = sigmoidf_(A2p[idx]);
        float A3 = sigmoidf_(A3p[idx]);
        float A4 = sigmoidf_(A4p[idx]);
        float B1 = sigmoidf_(B1p[idx]);
        float B2 = sigmoidf_(B2p[idx]);
        const float scale = 0.70710678118654752f;
        float C1 = C1p[idx] * scale;
        float C2 = C2p[idx] * scale;

        float xh_up[LSIDE], xv_up[LSIDE];
#pragma unroll
        for (int j = 0; j < LSIDE; j++) { xh_up[j] = 0.0f; xv_up[j] = 0.0f; }

        float* kout = &sk2[(nn << 2) + d][0];
        for (int i = 0; i < LSIDE; i++) {
            float xh_prev = 0.0f, xv_prev = 0.0f;
#pragma unroll
            for (int j = 0; j < LSIDE; j++) {
                float u = (i == 0 && j == 0) ? 1.0f : 0.0f;
                float xv_new  = A3 * xh_up[j] + A4 * xv_up[j] + B2 * u;
                float xv_left = (j == 0) ? 0.0f : xv_prev;
                float xh_new  = A1 * xh_prev + A2 * xv_left + B1 * u;
                kout[i * LSIDE + j] = C1 * xh_new + C2 * xv_new;
                xh_up[j] = xh_new; xv_up[j] = xv_new;
                xh_prev  = xh_new; xv_prev  = xv_new;
            }
        }
    }
    __syncthreads();

#pragma unroll
    for (int it = 0; it < 16; it++) {
        int idx = tid + it * 256;
        int d  = idx >> 10;
        int ab = idx & 1023;
        int a = ab >> 5, b = ab & 31;
        float v = sk2[d][ab] + sk2[4 + d][ab];
        float f = 1.0f;
        if (!(a == 0 && b == 0)) {
            if (a == 0) f *= 2.0f;
            if (b == 0) f *= 2.0f;
        }
        __syncwarp();
        sk2[d][ab] = v * f;
    }
    __syncthreads();

    auto Tval = [&](int da, int db) -> float {
        if (db > 31 || db < -31) return 0.0f;
        int a = da < 0 ? -da : da;
        int b = db < 0 ? -db : db;
        int idx = a * 32 + b;
        float r = 0.0f;
        if (da >= 0 && db >= 0) r += sk2[0][idx];
        if (da <= 0 && db >= 0) r += sk2[1][idx];
        if (da >= 0 && db <= 0) r += sk2[2][idx];
        if (da <= 0 && db <= 0) r += sk2[3][idx];
        return r;
    };

#pragma unroll
    for (int t = 0; t < 16; t++) {
        int e = tid + t * 256;
        if (e < TSZ) {
            int da = (e >> 6) - 31;
            int p  = e & 63;
            __half2 h = __floats2half2_rn(Tval(da, 32 - p), Tval(da, 31 - p));
            g_Tp[(size_t)n * TSZ + e] = *(uint32_t*)&h;
        }
    }
}

// ---------------------------------------------------------------------------
// Kernel 2: PERSISTENT Toeplitz HMMA GEMM. 740 CTAs (5/SM), 128 threads,
// 4 warps (warp tile 32x64). Each CTA loops over tiles (2048 total).
// Per tile: 128(M)x64(N), K=1024 in 16 chunks, 3-stage cp.async, one sync
// per chunk. Smem: 3 x 8KB B + 16128B table ~= 40KB.
// ---------------------------------------------------------------------------
#define GEMM_CTAS 740
#define NTILES    2048

__global__ __launch_bounds__(128) void gemm_kernel() {
    __shared__ __align__(1024) __half bbuf[3 * 64 * 64];    // 24 KB B stages
    __shared__ __align__(16) uint32_t spair[TSZ];           // 16128 B table

    const int tid = threadIdx.x;
    const int wm = tid >> 5;
    const int lane = tid & 31;
    const uint32_t sB = smem_u32(bbuf);
    const uint32_t sT = smem_u32(spair);
    const uint32_t B_STG = 8192;
    const int bRow0 = (lane & 7) + ((lane & 16) >> 1);
    const uint32_t bKsel = (uint32_t)((lane & 8) << 1);

    for (int tile = blockIdx.x; tile < NTILES; tile += GEMM_CTAS) {
        const int n  = tile >> 6;
        const int m0 = ((tile >> 3) & 7) << 7;
        const int n0 = (tile & 7) << 6;
        const __half* Bg = g_X + ((size_t)n << 19);

        // table load (cp.async group 0)
        {
            const uint32_t* src = g_Tp + (size_t)n * TSZ;
#pragma unroll
            for (int i = 0; i < 8; ++i) {
                int id = tid + (i << 7);
                if (id < TSZ / 4) cp_async16(sT + id * 16, src + id * 4);
            }
            cp_commit();
        }

        auto load_chunk = [&](int c, int st) {
            int k0 = c << 6;
#pragma unroll
            for (int i = 0; i < 4; ++i) {
                int id  = tid + (i << 7);
                int row = id >> 3, k8 = id & 7;
                uint32_t sw = (uint32_t)(row * 128 + ((k8 << 4) ^ ((row & 7) << 4)));
                cp_async16(sB + (uint32_t)st * B_STG + sw,
                           Bg + (size_t)(n0 + row) * 1024 + k0 + (k8 << 3));
            }
            cp_commit();
        };

        load_chunk(0, 0);
        load_chunk(1, 1);

        float acc[2][8][4];
#pragma unroll
        for (int mi = 0; mi < 2; mi++)
#pragma unroll
            for (int nj = 0; nj < 8; nj++)
#pragma unroll
                for (int q = 0; q < 4; q++) acc[mi][nj][q] = 0.0f;

        uint32_t pA0;
        {
            int sp = m0 + wm * 32 + (lane >> 2);
            int i = sp >> 5, j = sp & 31;
            pA0 = sT + (uint32_t)(((i + 31) * 64 + (32 - j) + (lane & 3) * 2) * 4);
        }

        int st = 0;
        for (int c = 0; c < 16; ++c) {
            if (c < 15) asm volatile("cp.async.wait_group 1;" ::: "memory");
            else        asm volatile("cp.async.wait_group 0;" ::: "memory");
            __syncthreads();

            if (c + 2 < 16) {
                int fs = st - 1; if (fs < 0) fs = 2;
                load_chunk(c + 2, fs);
            }

            uint32_t bS = sB + (uint32_t)st * B_STG;

#pragma unroll
            for (int us = 0; us < 2; ++us) {
                int u = 2 * c + us;
                uint32_t ub = pA0 - (uint32_t)(u << 8);

                uint32_t t[7];
#pragma unroll
                for (int w = 0; w < 7; ++w) t[w] = lds32(ub + (uint32_t)((w - 3) * 32));

#pragma unroll
                for (int kh = 0; kh < 2; ++kh) {
                    int ks = 2 * us + kh;
                    uint32_t b[4][4];
#pragma unroll
                    for (int p = 0; p < 4; p++) {
                        int row = bRow0 + p * 16;
                        uint32_t kb = (uint32_t)(ks << 5) + bKsel;
                        uint32_t addr = bS + (uint32_t)(row * 128)
                                      + (kb ^ (uint32_t)((row & 7) << 4));
                        ldsm_x4(b[p], addr);
                    }
                    int o = kh << 1;
#pragma unroll
                    for (int nj = 0; nj < 8; nj++) {
                        int p = nj >> 1, e = (nj & 1) << 1;
                        mma16816(acc[0][nj], t[3 + o], t[2 + o], t[4 + o], t[3 + o],
                                 b[p][e], b[p][e + 1]);
                        mma16816(acc[1][nj], t[1 + o], t[0 + o], t[2 + o], t[1 + o],
                                 b[p][e], b[p][e + 1]);
                    }
                }
            }
            if (++st == 3) st = 0;
        }

        // writeout accumulators as fp16 pairs
        __half* C = g_Outh + ((size_t)n << 19);
        int colBase = n0 + ((lane & 3) << 1);
        int rowBase = m0 + wm * 32 + (lane >> 2);
#pragma unroll
        for (int mi = 0; mi < 2; mi++) {
            int r = rowBase + mi * 16;
#pragma unroll
            for (int nj = 0; nj < 8; nj++) {
                int col = colBase + nj * 8;
                __half2 lo = __floats2half2_rn(acc[mi][nj][0], acc[mi][nj][1]);
                __half2 hi = __floats2half2_rn(acc[mi][nj][2], acc[mi][nj][3]);
                *(__half2*)&C[(size_t)r * GCOLS + col]       = lo;
                *(__half2*)&C[(size_t)(r + 8) * GCOLS + col] = hi;
            }
        }

        // protect table + B stage 0 before next tile's loads
        __syncthreads();
    }
}

// ---------------------------------------------------------------------------
// Kernel 3: un-gather Out(fp16) + residual x*omega + SiLU -> d_out fp32
// 8 s per block; uint4 gather; float4 x/out/omega; fast exp.
// ---------------------------------------------------------------------------
__global__ __launch_bounds__(512) void epilogue_kernel(const float* __restrict__ x,
                                                       const float* __restrict__ omega,
                                                       float* __restrict__ out) {
    int blk = blockIdx.x;                 // 0..4095
    int b  = blk & 31;
    int s0 = (blk >> 5) << 3;             // 8 consecutive s
    __shared__ float sm[8][16 * 33 + 16];
    int tid = threadIdx.x;                // 512

    // phase 1: one uint4 (8 halves = 8 r-values) per thread
    {
        int sv = tid >> 6;
        int q  = tid & 63;
        int nn = q >> 1;
        int r0 = (q & 1) << 3;
        uint4 v = *(const uint4*)&g_Outh[((size_t)nn << 19)
                                         + (size_t)(s0 + sv) * GCOLS + b * 16 + r0];
        const __half* hv = (const __half*)&v;
#pragma unroll
        for (int k = 0; k < 8; ++k)
            sm[sv][(r0 + k) * 33 + nn] = __half2float(hv[k]);
    }
    __syncthreads();

    // phase 2: float4 over (sv, e4): 1024 float4 positions, 2 per thread
#pragma unroll
    for (int i = 0; i < 2; ++i) {
        int idx = tid + (i << 9);         // 0..1023
        int sv = idx >> 7;
        int e0 = (idx & 127) << 2;
        float4 om = *(const float4*)&omega[e0];
        int r = e0 >> 5, nn = e0 & 31;
        const float* sp_ = &sm[sv][r * 33 + nn];
        size_t off = (size_t)(s0 + sv) * (BSZ * EMBED) + (size_t)b * EMBED + e0;
        float4 xv = *(const float4*)&x[off];
        float4 o;
        float z0 = fmaf(xv.x, om.x, sp_[0]);
        float z1 = fmaf(xv.y, om.y, sp_[1]);
        float z2 = fmaf(xv.z, om.z, sp_[2]);
        float z3 = fmaf(xv.w, om.w, sp_[3]);
        o.x = __fdividef(z0, 1.0f + __expf(-z0));
        o.y = __fdividef(z1, 1.0f + __expf(-z1));
        o.z = __fdividef(z2, 1.0f + __expf(-z2));
        o.w = __fdividef(z3, 1.0f + __expf(-z3));
        *(float4*)&out[off] = o;
    }
}

// ---------------------------------------------------------------------------
extern "C" void kernel_launch(void* const* d_in, const int* in_sizes, int n_in,
                              void* d_out, int out_size) {
    const float* x     = (const float*)d_in[0];
    const float* A1    = (const float*)d_in[1];
    const float* A2    = (const float*)d_in[2];
    const float* A3    = (const float*)d_in[3];
    const float* A4    = (const float*)d_in[4];
    const float* B1    = (const float*)d_in[5];
    const float* B2    = (const float*)d_in[6];
    const float* C1    = (const float*)d_in[7];
    const float* C2    = (const float*)d_in[8];
    const float* omega = (const float*)d_in[9];
    float* out = (float*)d_out;

    prep_kernel<<<TRB + GROUPS, 256>>>(x, A1, A2, A3, A4, B1, B2, C1, C2);
    gemm_kernel<<<GEMM_CTAS, 128>>>();
    epilogue_kernel<<<SEQ * BSZ / 8, 512>>>(x, omega, out);
}

// round 17
// speedup vs baseline: 1.5275x; 1.0290x over previous
#include <cuda_runtime.h>
#include <cuda_fp16.h>
#include <math.h>
#include <stdint.h>

// ---------------------------------------------------------------------------
// TwoDimensionalSSM: out = silu( conv4dir(x, k) + x*omega )
// M_n is 2-level Toeplitz: M[(i,j),(u,v)] = T_n(i-u, j-v), T = 63x63 table.
// Persistent Toeplitz HMMA GEMM + fused prep (warp-scan recurrence).
// ---------------------------------------------------------------------------

#define LSIDE  32
#define SEQ    1024
#define BSZ    32
#define EMBED  512
#define NSSM   32
#define GROUPS 32
#define GCOLS  512
#define TROWS  63
#define TCOLSW 64
#define TSZ    (TROWS * TCOLSW)   // 4032 uint32 per group

#define TRB 1024                   // transpose blocks = (SEQ/32) * BSZ = 32*32

// Static device scratch (allocation-free, graph-capturable)
__device__ __align__(16) uint32_t g_Tp[(size_t)GROUPS * TSZ];        // 516 KB pair tables
__device__ __align__(16) __half g_X[(size_t)GROUPS * GCOLS * 1024];  // 32 MB  [n][c][s]
__device__ __align__(16) __half g_Outh[(size_t)GROUPS * 1024 * GCOLS]; // 32 MB [n][sp][c]

__device__ __forceinline__ float sigmoidf_(float v) { return 1.0f / (1.0f + expf(-v)); }

__device__ __forceinline__ uint32_t smem_u32(const void* p) {
    return (uint32_t)__cvta_generic_to_shared(p);
}
__device__ __forceinline__ void cp_async16(uint32_t dst, const void* src) {
    asm volatile("cp.async.cg.shared.global [%0], [%1], 16;" :: "r"(dst), "l"(src) : "memory");
}
__device__ __forceinline__ void cp_commit() {
    asm volatile("cp.async.commit_group;" ::: "memory");
}
__device__ __forceinline__ uint32_t lds32(uint32_t addr) {
    uint32_t v;
    asm volatile("ld.shared.b32 %0, [%1];" : "=r"(v) : "r"(addr));
    return v;
}
__device__ __forceinline__ void ldsm_x4(uint32_t* r, uint32_t addr) {
    asm volatile("ldmatrix.sync.aligned.m8n8.x4.shared.b16 {%0,%1,%2,%3}, [%4];"
                 : "=r"(r[0]), "=r"(r[1]), "=r"(r[2]), "=r"(r[3]) : "r"(addr));
}
__device__ __forceinline__ void mma16816(float* c, uint32_t a0, uint32_t a1, uint32_t a2,
                                         uint32_t a3, uint32_t b0, uint32_t b1) {
    asm volatile(
        "mma.sync.aligned.m16n8k16.row.col.f32.f16.f16.f32 "
        "{%0,%1,%2,%3}, {%4,%5,%6,%7}, {%8,%9}, {%0,%1,%2,%3};"
        : "+f"(c[0]), "+f"(c[1]), "+f"(c[2]), "+f"(c[3])
        : "r"(a0), "r"(a1), "r"(a2), "r"(a3), "r"(b0), "r"(b1));
}

// ---------------------------------------------------------------------------
// Kernel 1 (fused prep): blocks [0, TRB) transpose x -> g_X; blocks
// [TRB, TRB+32) build the Toeplitz pair tables.
// Recurrence: 8 warps, one per (dir, state); lane j = column j.
// Horizontal recurrence via Kogge-Stone affine scan (5 shfl steps).
// ---------------------------------------------------------------------------
__global__ __launch_bounds__(256) void prep_kernel(
        const float* __restrict__ x,
        const float* __restrict__ A1p, const float* __restrict__ A2p,
        const float* __restrict__ A3p, const float* __restrict__ A4p,
        const float* __restrict__ B1p, const float* __restrict__ B2p,
        const float* __restrict__ C1p, const float* __restrict__ C2p) {
    __shared__ __align__(16) char smraw[33664];
    int tid = threadIdx.x;

    if (blockIdx.x < TRB) {
        // ---- transpose: x (S,B,E) fp32 -> g_X[n][c][s] fp16, c=b*16+e/32 ----
        __half (*sm)[520] = (__half(*)[520])smraw;
        int b  = blockIdx.x & 31;
        int s0 = (blockIdx.x >> 5) << 5;
#pragma unroll
        for (int i = 0; i < 16; ++i) {
            int idx4 = tid + (i << 8);
            int si = idx4 >> 7;
            int e  = (idx4 & 127) << 2;
            float4 v = *(const float4*)&x[(size_t)(s0 + si) * (BSZ * EMBED)
                                          + (size_t)b * EMBED + e];
            *(__half2*)&sm[si][e]     = __floats2half2_rn(v.x, v.y);
            *(__half2*)&sm[si][e + 2] = __floats2half2_rn(v.z, v.w);
        }
        __syncthreads();
#pragma unroll
        for (int i = 0; i < 8; ++i) {
            int c2 = tid + (i << 8);
            int pair = c2 >> 2, sj = (c2 & 3) << 3;
            int nn = pair & 31, r = pair >> 5;
            int e = (r << 5) + nn;
            __half tmp[8];
#pragma unroll
            for (int q = 0; q < 8; ++q) tmp[q] = sm[sj + q][e];
            *(uint4*)&g_X[((size_t)nn * GCOLS + b * 16 + r) * 1024 + s0 + sj] = *(uint4*)tmp;
        }
        return;
    }

    // ---- build_T for group n ----
    int n = blockIdx.x - TRB;
    float (*sk2)[1024] = (float(*)[1024])smraw;

    {
        int w = tid >> 5;          // warp = (d, nn) pair
        int lane = tid & 31;       // lane = column j
        int d = w >> 1, nn = w & 1;
        int h = d * NSSM + n;
        int idx = h * 2 + nn;
        float A1 = sigmoidf_(A1p[idx]);
        float A2 = sigmoidf_(A2p[idx]);
        float A3 = sigmoidf_(A3p[idx]);
        float A4 = sigmoidf_(A4p[idx]);
        float B1 = sigmoidf_(B1p[idx]);
        float B2 = sigmoidf_(B2p[idx]);
        const float scale = 0.70710678118654752f;
        float C1 = C1p[idx] * scale;
        float C2 = C2p[idx] * scale;

        float xh_up = 0.0f, xv_up = 0.0f;   // previous-row states, this column
        float* kout = &sk2[(nn << 2) + d][0];

        for (int i = 0; i < LSIDE; i++) {
            float u = (i == 0 && lane == 0) ? 1.0f : 0.0f;
            float xv_new = A3 * xh_up + A4 * xv_up + B2 * u;
            float xv_left = __shfl_up_sync(0xffffffffu, xv_new, 1);
            if (lane == 0) xv_left = 0.0f;

            // xh[j] = A1*xh[j-1] + b[j], xh[-1] = 0: affine Kogge-Stone scan
            float a = A1;
            float bb = fmaf(A2, xv_left, B1 * u);
#pragma unroll
            for (int off = 1; off < 32; off <<= 1) {
                float ap = __shfl_up_sync(0xffffffffu, a, off);
                float bp = __shfl_up_sync(0xffffffffu, bb, off);
                if (lane >= off) {
                    bb = fmaf(a, bp, bb);
                    a  = a * ap;
                }
            }
            float xh_new = bb;     // since xh[-1] = 0

            kout[i * LSIDE + lane] = C1 * xh_new + C2 * xv_new;
            xh_up = xh_new;
            xv_up = xv_new;
        }
    }
    __syncthreads();

    // combine nn-partials + boundary factors, in place into sk2[d][ab]
#pragma unroll
    for (int it = 0; it < 16; it++) {
        int idx = tid + it * 256;
        int d  = idx >> 10;
        int ab = idx & 1023;
        int a = ab >> 5, b = ab & 31;
        float v = sk2[d][ab] + sk2[4 + d][ab];
        float f = 1.0f;
        if (!(a == 0 && b == 0)) {
            if (a == 0) f *= 2.0f;
            if (b == 0) f *= 2.0f;
        }
        __syncwarp();
        sk2[d][ab] = v * f;
    }
    __syncthreads();

    auto Tval = [&](int da, int db) -> float {
        if (db > 31 || db < -31) return 0.0f;
        int a = da < 0 ? -da : da;
        int b = db < 0 ? -db : db;
        int idx = a * 32 + b;
        float r = 0.0f;
        if (da >= 0 && db >= 0) r += sk2[0][idx];
        if (da <= 0 && db >= 0) r += sk2[1][idx];
        if (da >= 0 && db <= 0) r += sk2[2][idx];
        if (da <= 0 && db <= 0) r += sk2[3][idx];
        return r;
    };

#pragma unroll
    for (int t = 0; t < 16; t++) {
        int e = tid + t * 256;
        if (e < TSZ) {
            int da = (e >> 6) - 31;
            int p  = e & 63;
            __half2 h = __floats2half2_rn(Tval(da, 32 - p), Tval(da, 31 - p));
            g_Tp[(size_t)n * TSZ + e] = *(uint32_t*)&h;
        }
    }
}

// ---------------------------------------------------------------------------
// Kernel 2: PERSISTENT Toeplitz HMMA GEMM. 740 CTAs (5/SM), 128 threads,
// 4 warps (warp tile 32x64). Each CTA loops over tiles (2048 total).
// Per tile: 128(M)x64(N), K=1024 in 16 chunks, 3-stage cp.async, one sync
// per chunk. Smem: 3 x 8KB B + 16128B table ~= 40KB.
// ---------------------------------------------------------------------------
#define GEMM_CTAS 740
#define NTILES    2048

__global__ __launch_bounds__(128) void gemm_kernel() {
    __shared__ __align__(1024) __half bbuf[3 * 64 * 64];    // 24 KB B stages
    __shared__ __align__(16) uint32_t spair[TSZ];           // 16128 B table

    const int tid = threadIdx.x;
    const int wm = tid >> 5;
    const int lane = tid & 31;
    const uint32_t sB = smem_u32(bbuf);
    const uint32_t sT = smem_u32(spair);
    const uint32_t B_STG = 8192;
    const int bRow0 = (lane & 7) + ((lane & 16) >> 1);
    const uint32_t bKsel = (uint32_t)((lane & 8) << 1);

    for (int tile = blockIdx.x; tile < NTILES; tile += GEMM_CTAS) {
        const int n  = tile >> 6;
        const int m0 = ((tile >> 3) & 7) << 7;
        const int n0 = (tile & 7) << 6;
        const __half* Bg = g_X + ((size_t)n << 19);

        // table load (cp.async group 0)
        {
            const uint32_t* src = g_Tp + (size_t)n * TSZ;
#pragma unroll
            for (int i = 0; i < 8; ++i) {
                int id = tid + (i << 7);
                if (id < TSZ / 4) cp_async16(sT + id * 16, src + id * 4);
            }
            cp_commit();
        }

        auto load_chunk = [&](int c, int st) {
            int k0 = c << 6;
#pragma unroll
            for (int i = 0; i < 4; ++i) {
                int id  = tid + (i << 7);
                int row = id >> 3, k8 = id & 7;
                uint32_t sw = (uint32_t)(row * 128 + ((k8 << 4) ^ ((row & 7) << 4)));
                cp_async16(sB + (uint32_t)st * B_STG + sw,
                           Bg + (size_t)(n0 + row) * 1024 + k0 + (k8 << 3));
            }
            cp_commit();
        };

        load_chunk(0, 0);
        load_chunk(1, 1);

        float acc[2][8][4];
#pragma unroll
        for (int mi = 0; mi < 2; mi++)
#pragma unroll
            for (int nj = 0; nj < 8; nj++)
#pragma unroll
                for (int q = 0; q < 4; q++) acc[mi][nj][q] = 0.0f;

        uint32_t pA0;
        {
            int sp = m0 + wm * 32 + (lane >> 2);
            int i = sp >> 5, j = sp & 31;
            pA0 = sT + (uint32_t)(((i + 31) * 64 + (32 - j) + (lane & 3) * 2) * 4);
        }

        int st = 0;
        for (int c = 0; c < 16; ++c) {
            if (c < 15) asm volatile("cp.async.wait_group 1;" ::: "memory");
            else        asm volatile("cp.async.wait_group 0;" ::: "memory");
            __syncthreads();

            if (c + 2 < 16) {
                int fs = st - 1; if (fs < 0) fs = 2;
                load_chunk(c + 2, fs);
            }

            uint32_t bS = sB + (uint32_t)st * B_STG;

#pragma unroll
            for (int us = 0; us < 2; ++us) {
                int u = 2 * c + us;
                uint32_t ub = pA0 - (uint32_t)(u << 8);

                uint32_t t[7];
#pragma unroll
                for (int w = 0; w < 7; ++w) t[w] = lds32(ub + (uint32_t)((w - 3) * 32));

#pragma unroll
                for (int kh = 0; kh < 2; ++kh) {
                    int ks = 2 * us + kh;
                    uint32_t b[4][4];
#pragma unroll
                    for (int p = 0; p < 4; p++) {
                        int row = bRow0 + p * 16;
                        uint32_t kb = (uint32_t)(ks << 5) + bKsel;
                        uint32_t addr = bS + (uint32_t)(row * 128)
                                      + (kb ^ (uint32_t)((row & 7) << 4));
                        ldsm_x4(b[p], addr);
                    }
                    int o = kh << 1;
#pragma unroll
                    for (int nj = 0; nj < 8; nj++) {
                        int p = nj >> 1, e = (nj & 1) << 1;
                        mma16816(acc[0][nj], t[3 + o], t[2 + o], t[4 + o], t[3 + o],
                                 b[p][e], b[p][e + 1]);
                        mma16816(acc[1][nj], t[1 + o], t[0 + o], t[2 + o], t[1 + o],
                                 b[p][e], b[p][e + 1]);
                    }
                }
            }
            if (++st == 3) st = 0;
        }

        // writeout accumulators as fp16 pairs
        __half* C = g_Outh + ((size_t)n << 19);
        int colBase = n0 + ((lane & 3) << 1);
        int rowBase = m0 + wm * 32 + (lane >> 2);
#pragma unroll
        for (int mi = 0; mi < 2; mi++) {
            int r = rowBase + mi * 16;
#pragma unroll
            for (int nj = 0; nj < 8; nj++) {
                int col = colBase + nj * 8;
                __half2 lo = __floats2half2_rn(acc[mi][nj][0], acc[mi][nj][1]);
                __half2 hi = __floats2half2_rn(acc[mi][nj][2], acc[mi][nj][3]);
                *(__half2*)&C[(size_t)r * GCOLS + col]       = lo;
                *(__half2*)&C[(size_t)(r + 8) * GCOLS + col] = hi;
            }
        }

        // protect table + B stage 0 before next tile's loads
        __syncthreads();
    }
}

// ---------------------------------------------------------------------------
// Kernel 3: un-gather Out(fp16) + residual x*omega + SiLU -> d_out fp32
// 8 s per block; uint4 gather; float4 x/out/omega; fast exp.
// ---------------------------------------------------------------------------
__global__ __launch_bounds__(512) void epilogue_kernel(const float* __restrict__ x,
                                                       const float* __restrict__ omega,
                                                       float* __restrict__ out) {
    int blk = blockIdx.x;                 // 0..4095
    int b  = blk & 31;
    int s0 = (blk >> 5) << 3;             // 8 consecutive s
    __shared__ float sm[8][16 * 33 + 16];
    int tid = threadIdx.x;                // 512

    // phase 1: one uint4 (8 halves = 8 r-values) per thread
    {
        int sv = tid >> 6;
        int q  = tid & 63;
        int nn = q >> 1;
        int r0 = (q & 1) << 3;
        uint4 v = *(const uint4*)&g_Outh[((size_t)nn << 19)
                                         + (size_t)(s0 + sv) * GCOLS + b * 16 + r0];
        const __half* hv = (const __half*)&v;
#pragma unroll
        for (int k = 0; k < 8; ++k)
            sm[sv][(r0 + k) * 33 + nn] = __half2float(hv[k]);
    }
    __syncthreads();

    // phase 2: float4 over (sv, e4): 1024 float4 positions, 2 per thread
#pragma unroll
    for (int i = 0; i < 2; ++i) {
        int idx = tid + (i << 9);         // 0..1023
        int sv = idx >> 7;
        int e0 = (idx & 127) << 2;
        float4 om = *(const float4*)&omega[e0];
        int r = e0 >> 5, nn = e0 & 31;
        const float* sp_ = &sm[sv][r * 33 + nn];
        size_t off = (size_t)(s0 + sv) * (BSZ * EMBED) + (size_t)b * EMBED + e0;
        float4 xv = *(const float4*)&x[off];
        float4 o;
        float z0 = fmaf(xv.x, om.x, sp_[0]);
        float z1 = fmaf(xv.y, om.y, sp_[1]);
        float z2 = fmaf(xv.z, om.z, sp_[2]);
        float z3 = fmaf(xv.w, om.w, sp_[3]);
        o.x = __fdividef(z0, 1.0f + __expf(-z0));
        o.y = __fdividef(z1, 1.0f + __expf(-z1));
        o.z = __fdividef(z2, 1.0f + __expf(-z2));
        o.w = __fdividef(z3, 1.0f + __expf(-z3));
        *(float4*)&out[off] = o;
    }
}

// ---------------------------------------------------------------------------
extern "C" void kernel_launch(void* const* d_in, const int* in_sizes, int n_in,
                              void* d_out, int out_size) {
    const float* x     = (const float*)d_in[0];
    const float* A1    = (const float*)d_in[1];
    const float* A2    = (const float*)d_in[2];
    const float* A3    = (const float*)d_in[3];
    const float* A4    = (const float*)d_in[4];
    const float* B1    = (const float*)d_in[5];
    const float* B2    = (const float*)d_in[6];
    const float* C1    = (const float*)d_in[7];
    const float* C2    = (const float*)d_in[8];
    const float* omega = (const float*)d_in[9];
    float* out = (float*)d_out;

    prep_kernel<<<TRB + GROUPS, 256>>>(x, A1, A2, A3, A4, B1, B2, C1, C2);
    gemm_kernel<<<GEMM_CTAS, 128>>>();
    epilogue_kernel<<<SEQ * BSZ / 8, 512>>>(x, omega, out);
}